// round 3
// baseline (speedup 1.0000x reference)
#include <cuda_runtime.h>
#include <math.h>

#define B_DIM 2
#define C_DIM 256
#define N_POS 4096
#define G_GROUPS 32
#define CPG 8           // channels per group
#define EPS 1e-6f

// ---------------- scratch (device globals; no allocation allowed) ----------------
__device__ float g_hn [(size_t)B_DIM * C_DIM * N_POS];
__device__ float g_q  [(size_t)B_DIM * C_DIM * N_POS];
__device__ float g_k  [(size_t)B_DIM * C_DIM * N_POS];
__device__ float g_v  [(size_t)B_DIM * C_DIM * N_POS];
__device__ float g_hv [(size_t)B_DIM * C_DIM * N_POS];
__device__ float g_attn[(size_t)B_DIM * N_POS * N_POS];   // 128 MB

// ---------------- GroupNorm: one block per (batch, group) ----------------
__global__ void __launch_bounds__(256) groupnorm_kernel(
    const float* __restrict__ x, const float* __restrict__ gamma,
    const float* __restrict__ beta, float* __restrict__ hn)
{
    const int bg = blockIdx.x;              // 0..63
    const int b = bg / G_GROUPS, g = bg % G_GROUPS;
    const size_t base = ((size_t)b * C_DIM + (size_t)g * CPG) * N_POS;
    const float* xp = x + base;
    float* hp = hn + base;
    const int tid = threadIdx.x;
    const int NEL = CPG * N_POS;            // 32768

    float s = 0.f, s2 = 0.f;
    for (int i = tid; i < NEL; i += 256) {
        float v = xp[i];
        s += v; s2 += v * v;
    }
    __shared__ float sh0[256], sh1[256];
    sh0[tid] = s; sh1[tid] = s2;
    __syncthreads();
    for (int o = 128; o > 0; o >>= 1) {
        if (tid < o) { sh0[tid] += sh0[tid + o]; sh1[tid] += sh1[tid + o]; }
        __syncthreads();
    }
    const float mean = sh0[0] * (1.0f / NEL);
    const float var  = sh1[0] * (1.0f / NEL) - mean * mean;
    const float rstd = rsqrtf(var + EPS);

    for (int i = tid; i < NEL; i += 256) {
        const int cc = i >> 12;             // i / N_POS
        const int c  = g * CPG + cc;
        hp[i] = (xp[i] - mean) * rstd * gamma[c] + beta[c];
    }
}

// ---------------- generic 64x64x16 tiled SGEMM ----------------
// C[m,n] = alpha * sum_k opA(A)[m,k] * opB(B)[k,n]  (+ bias[m]) (+ res[m,n])
//   TA=0: A is M x K (row-major, lda)     TA=1: A is K x M (row-major, lda)
//   TB=0: B is K x N (row-major, ldb)     TB=1: B is N x K (row-major, ldb)
// blockIdx.z = batch; sA/sB/sC are per-batch element strides (sA=0 for shared weights).
// All dims assumed multiples of the tile sizes (true here: 256/4096, K in {256,4096}).
template<int TA, int TB>
__global__ void __launch_bounds__(256) gemm64(
    const float* __restrict__ A, const float* __restrict__ B, float* __restrict__ Cc,
    int M, int N, int K, int lda, int ldb, int ldc,
    const float* __restrict__ bias, const float* __restrict__ res,
    float alpha, size_t sA, size_t sB, size_t sC)
{
    __shared__ __align__(16) float As[16][68];
    __shared__ __align__(16) float Bs[16][68];

    const int bz = blockIdx.z;
    A  += sA * bz;
    B  += sB * bz;
    Cc += sC * bz;
    const float* Res = res ? res + sC * bz : nullptr;

    const int n0 = blockIdx.x * 64;
    const int m0 = blockIdx.y * 64;
    const int tid = threadIdx.x;
    const int tx = tid & 15;                 // n micro-tile
    const int ty = tid >> 4;                 // m micro-tile

    float acc[4][4] = {};

    for (int k0 = 0; k0 < K; k0 += 16) {
        // load A tile -> As[k][m]
        #pragma unroll
        for (int i = 0; i < 4; i++) {
            const int lin = tid + i * 256;
            if (TA == 0) {
                const int kk = lin & 15, mm = lin >> 4;
                As[kk][mm] = A[(size_t)(m0 + mm) * lda + (k0 + kk)];
            } else {
                const int mm = lin & 63, kk = lin >> 6;
                As[kk][mm] = A[(size_t)(k0 + kk) * lda + (m0 + mm)];
            }
        }
        // load B tile -> Bs[k][n]
        #pragma unroll
        for (int i = 0; i < 4; i++) {
            const int lin = tid + i * 256;
            if (TB == 0) {
                const int nn = lin & 63, kk = lin >> 6;
                Bs[kk][nn] = B[(size_t)(k0 + kk) * ldb + (n0 + nn)];
            } else {
                const int kk = lin & 15, nn = lin >> 4;
                Bs[kk][nn] = B[(size_t)(n0 + nn) * ldb + (k0 + kk)];
            }
        }
        __syncthreads();

        #pragma unroll
        for (int kk = 0; kk < 16; kk++) {
            const float4 a4 = *(const float4*)&As[kk][ty * 4];
            const float4 b4 = *(const float4*)&Bs[kk][tx * 4];
            const float a[4] = {a4.x, a4.y, a4.z, a4.w};
            const float b[4] = {b4.x, b4.y, b4.z, b4.w};
            #pragma unroll
            for (int i = 0; i < 4; i++)
                #pragma unroll
                for (int j = 0; j < 4; j++)
                    acc[i][j] += a[i] * b[j];
        }
        __syncthreads();
    }

    #pragma unroll
    for (int i = 0; i < 4; i++) {
        const int m = m0 + ty * 4 + i;
        const float bi = bias ? bias[m] : 0.f;
        #pragma unroll
        for (int j = 0; j < 4; j++) {
            const int n = n0 + tx * 4 + j;
            float v = acc[i][j] * alpha + bi;
            if (res) v += Res[(size_t)m * ldc + n];
            Cc[(size_t)m * ldc + n] = v;
        }
    }
}

// ---------------- row softmax over the attn scratch (rows of length 4096) ----------------
__global__ void __launch_bounds__(256) softmax_kernel(float* __restrict__ attn)
{
    float* p = attn + (size_t)blockIdx.x * N_POS;
    const int tid = threadIdx.x;
    float v[16];
    float mx = -1e30f;
    #pragma unroll
    for (int i = 0; i < 16; i++) {
        v[i] = p[tid + i * 256];
        mx = fmaxf(mx, v[i]);
    }
    __shared__ float sh[256];
    sh[tid] = mx;
    __syncthreads();
    for (int o = 128; o > 0; o >>= 1) {
        if (tid < o) sh[tid] = fmaxf(sh[tid], sh[tid + o]);
        __syncthreads();
    }
    mx = sh[0];
    __syncthreads();

    float s = 0.f;
    #pragma unroll
    for (int i = 0; i < 16; i++) {
        v[i] = __expf(v[i] - mx);
        s += v[i];
    }
    sh[tid] = s;
    __syncthreads();
    for (int o = 128; o > 0; o >>= 1) {
        if (tid < o) sh[tid] += sh[tid + o];
        __syncthreads();
    }
    const float inv = 1.0f / sh[0];
    #pragma unroll
    for (int i = 0; i < 16; i++)
        p[tid + i * 256] = v[i] * inv;
}

// ---------------- tiled transpose: out2[b][m][n] = attn[b][n][m] ----------------
__global__ void __launch_bounds__(256) transpose_kernel(
    const float* __restrict__ attn, float* __restrict__ out2)
{
    __shared__ float tile[32][33];
    const int b  = blockIdx.z;
    const int n0 = blockIdx.x * 32;
    const int m0 = blockIdx.y * 32;
    const float* src = attn + (size_t)b * N_POS * N_POS;
    float*       dst = out2 + (size_t)b * N_POS * N_POS;
    const int tx = threadIdx.x;   // 0..31
    const int ty = threadIdx.y;   // 0..7
    #pragma unroll
    for (int j = 0; j < 4; j++)
        tile[ty + j * 8][tx] = src[(size_t)(n0 + ty + j * 8) * N_POS + (m0 + tx)];
    __syncthreads();
    #pragma unroll
    for (int j = 0; j < 4; j++)
        dst[(size_t)(m0 + ty + j * 8) * N_POS + (n0 + tx)] = tile[tx][ty + j * 8];
}

// ---------------- launch ----------------
extern "C" void kernel_launch(void* const* d_in, const int* in_sizes, int n_in,
                              void* d_out, int out_size)
{
    const float* x     = (const float*)d_in[0];
    const float* gamma = (const float*)d_in[1];
    const float* beta  = (const float*)d_in[2];
    const float* wq    = (const float*)d_in[3];
    const float* bq    = (const float*)d_in[4];
    const float* wk    = (const float*)d_in[5];
    const float* bk    = (const float*)d_in[6];
    const float* wv    = (const float*)d_in[7];
    const float* bv    = (const float*)d_in[8];
    const float* wp    = (const float*)d_in[9];
    const float* bp    = (const float*)d_in[10];

    float* out1 = (float*)d_out;
    float* out2 = out1 + (size_t)B_DIM * C_DIM * N_POS;

    float *hn, *q, *k, *v, *hv, *attn;
    cudaGetSymbolAddress((void**)&hn,   g_hn);
    cudaGetSymbolAddress((void**)&q,    g_q);
    cudaGetSymbolAddress((void**)&k,    g_k);
    cudaGetSymbolAddress((void**)&v,    g_v);
    cudaGetSymbolAddress((void**)&hv,   g_hv);
    cudaGetSymbolAddress((void**)&attn, g_attn);

    const size_t CN  = (size_t)C_DIM * N_POS;   // per-batch stride of (c,n) tensors
    const size_t NN2 = (size_t)N_POS * N_POS;   // per-batch stride of attn
    const float scale = 0.0625f;                // 256^-0.5

    // 1) GroupNorm -> hn
    groupnorm_kernel<<<B_DIM * G_GROUPS, 256>>>(x, gamma, beta, hn);

    // 2) q/k/v = W * hn + b   (M=256, N=4096, K=256), NN
    dim3 gproj(N_POS / 64, C_DIM / 64, B_DIM);   // (64, 4, 2)
    gemm64<0, 0><<<gproj, 256>>>(wq, hn, q, C_DIM, N_POS, C_DIM,
                                 C_DIM, N_POS, N_POS, bq, nullptr, 1.f, 0, CN, CN);
    gemm64<0, 0><<<gproj, 256>>>(wk, hn, k, C_DIM, N_POS, C_DIM,
                                 C_DIM, N_POS, N_POS, bk, nullptr, 1.f, 0, CN, CN);
    gemm64<0, 0><<<gproj, 256>>>(wv, hn, v, C_DIM, N_POS, C_DIM,
                                 C_DIM, N_POS, N_POS, bv, nullptr, 1.f, 0, CN, CN);

    // 3) s[n,m] = scale * sum_c q[c,n] k[c,m]   (M=N=4096, K=256), TN
    dim3 gs(N_POS / 64, N_POS / 64, B_DIM);      // (64, 64, 2)
    gemm64<1, 0><<<gs, 256>>>(q, k, attn, N_POS, N_POS, C_DIM,
                              N_POS, N_POS, N_POS, nullptr, nullptr, scale, CN, CN, NN2);

    // 4) row softmax over m
    softmax_kernel<<<B_DIM * N_POS, 256>>>(attn);

    // 5) hv[c,n] = sum_m v[c,m] attn[n,m]   (M=256, N=4096, K=4096), NT
    gemm64<0, 1><<<gproj, 256>>>(v, attn, hv, C_DIM, N_POS, N_POS,
                                 N_POS, N_POS, N_POS, nullptr, nullptr, 1.f, CN, NN2, CN);

    // 6) out1 = x + wp * hv + bp   (NN with residual)
    gemm64<0, 0><<<gproj, 256>>>(wp, hv, out1, C_DIM, N_POS, C_DIM,
                                 C_DIM, N_POS, N_POS, bp, x, 1.f, 0, CN, CN);

    // 7) out2[b,m,n] = attn[b,n,m]
    transpose_kernel<<<dim3(N_POS / 32, N_POS / 32, B_DIM), dim3(32, 8)>>>(attn, out2);
}

// round 6
// speedup vs baseline: 1.1130x; 1.1130x over previous
#include <cuda_runtime.h>
#include <math.h>
#include <stdint.h>

#define B_DIM 2
#define C_DIM 256
#define N_POS 4096
#define G_GROUPS 32
#define CPG 8
#define EPS 1e-6f

// ---------------- scratch (device globals; no allocation allowed) ----------------
__device__ float g_hn [(size_t)B_DIM * C_DIM * N_POS];
__device__ float g_q  [(size_t)B_DIM * C_DIM * N_POS];
__device__ float g_k  [(size_t)B_DIM * C_DIM * N_POS];
__device__ float g_v  [(size_t)B_DIM * C_DIM * N_POS];
__device__ float g_hv [(size_t)B_DIM * C_DIM * N_POS];
__device__ float g_attn[(size_t)B_DIM * N_POS * N_POS];   // 128 MB

// =================== tf32 helpers (plain sm_80+ PTX; works on sm_103 target) ===================
__device__ __forceinline__ uint32_t cvt_tf32(float x) {
    uint32_t u;
    asm("cvt.rna.tf32.f32 %0, %1;" : "=r"(u) : "f"(x));
    return u;
}

__device__ __forceinline__ void mma_tf32(float* c, const uint32_t* a,
                                         uint32_t b0, uint32_t b1) {
    asm volatile(
        "mma.sync.aligned.m16n8k8.row.col.f32.tf32.tf32.f32 "
        "{%0,%1,%2,%3}, {%4,%5,%6,%7}, {%8,%9}, {%0,%1,%2,%3};"
        : "+f"(c[0]), "+f"(c[1]), "+f"(c[2]), "+f"(c[3])
        : "r"(a[0]), "r"(a[1]), "r"(a[2]), "r"(a[3]), "r"(b0), "r"(b1));
}

// =================== tile staging ===================
// smem tile layout: [row 0..127][k 0..31], row stride S words.
//   MODE=1 ("T"): source is [row][k] row-major  -> natural float4 copy (S=36: conflict-free)
//   MODE=0 ("D"): source is [k][row] row-major  -> transpose scatter    (S=33: conflict-free STS)
template<int MODE>
__device__ __forceinline__ float4 tl_ldg(const float* __restrict__ src, int ld,
                                         int r0, int k0, int p) {
    if (MODE) {
        int kq = p & 7, r = p >> 3;
        return *(const float4*)(src + (size_t)(r0 + r) * ld + (k0 + 4 * kq));
    } else {
        int rqt = (p & 7) | (((p >> 8) & 3) << 3);         // 0..31 (float4 index along row dim)
        int k   = ((p >> 3) & 3) | (((p >> 5) & 7) << 2);  // 0..31
        return *(const float4*)(src + (size_t)(k0 + k) * ld + (r0 + 4 * rqt));
    }
}

template<int MODE, int S>
__device__ __forceinline__ void tl_sts(float4 v, uint32_t* __restrict__ hi,
                                       uint32_t* __restrict__ lo, int p) {
    float xs[4] = {v.x, v.y, v.z, v.w};
    uint32_t h[4], l[4];
    #pragma unroll
    for (int j = 0; j < 4; j++) {
        h[j] = cvt_tf32(xs[j]);
        l[j] = cvt_tf32(xs[j] - __uint_as_float(h[j]));
    }
    if (MODE) {
        int kq = p & 7, r = p >> 3;
        *(uint4*)(hi + r * S + 4 * kq) = make_uint4(h[0], h[1], h[2], h[3]);
        *(uint4*)(lo + r * S + 4 * kq) = make_uint4(l[0], l[1], l[2], l[3]);
    } else {
        int rqt = (p & 7) | (((p >> 8) & 3) << 3);
        int k   = ((p >> 3) & 3) | (((p >> 5) & 7) << 2);
        #pragma unroll
        for (int j = 0; j < 4; j++) {
            hi[(4 * rqt + j) * S + k] = h[j];
            lo[(4 * rqt + j) * S + k] = l[j];
        }
    }
}

// =================== HMMA tf32-split GEMM ===================
// C[m,n] = alpha * sum_k A[m,k]*B[n,k] (+bias[m]) (+res[m,n])
// CTA tile 128x128, K-chunk 32, 512 threads (16 warps, 4x4 warp grid, 32x32 warp tiles),
// double-buffered smem, split precision: hi*hi + hi*lo + lo*hi.
template<int MA, int MB>
__global__ void __launch_bounds__(512) gemm_tc(
    const float* __restrict__ A, const float* __restrict__ B, float* __restrict__ C,
    int K, int lda, int ldb, int ldc,
    const float* __restrict__ bias, const float* __restrict__ res, float alpha,
    size_t strA, size_t strB, size_t strC)
{
    constexpr int SA = MA ? 36 : 33;
    constexpr int SB = MB ? 36 : 33;
    constexpr int TA_W = 128 * SA;
    constexpr int TB_W = 128 * SB;
    constexpr int BUF_W = 2 * TA_W + 2 * TB_W;

    extern __shared__ __align__(16) uint32_t sm[];

    const int tid = threadIdx.x;
    const int lane = tid & 31, wid = tid >> 5;
    const int warp_m = wid & 3, warp_n = wid >> 2;
    const int gid = lane >> 2, tig = lane & 3;

    const int bz = blockIdx.z;
    A += strA * bz;
    B += strB * bz;
    C += strC * bz;
    const float* Res = res ? res + strC * bz : nullptr;
    const int n0 = blockIdx.x * 128, m0 = blockIdx.y * 128;

    float acc[2][4][4];
    #pragma unroll
    for (int i = 0; i < 2; i++)
        #pragma unroll
        for (int j = 0; j < 4; j++)
            #pragma unroll
            for (int t = 0; t < 4; t++) acc[i][j][t] = 0.f;

    // ---- load chunk 0 into buffer 0 ----
    #pragma unroll
    for (int s = 0; s < 2; s++) {
        int p = tid + s * 512;
        float4 va = tl_ldg<MA>(A, lda, m0, 0, p);
        tl_sts<MA, SA>(va, sm, sm + TA_W, p);
        float4 vb = tl_ldg<MB>(B, ldb, n0, 0, p);
        tl_sts<MB, SB>(vb, sm + 2 * TA_W, sm + 2 * TA_W + TB_W, p);
    }
    __syncthreads();

    const int nc = K >> 5;
    for (int c = 0; c < nc; c++) {
        const int cur = c & 1;
        const uint32_t* Ah = sm + cur * BUF_W;
        const uint32_t* Al = Ah + TA_W;
        const uint32_t* Bh = Ah + 2 * TA_W;
        const uint32_t* Bl = Bh + TB_W;

        // prefetch next chunk (global -> regs) before consuming current
        float4 pva[2], pvb[2];
        const bool pf = (c + 1 < nc);
        if (pf) {
            const int k0 = (c + 1) << 5;
            #pragma unroll
            for (int s = 0; s < 2; s++) {
                pva[s] = tl_ldg<MA>(A, lda, m0, k0, tid + s * 512);
                pvb[s] = tl_ldg<MB>(B, ldb, n0, k0, tid + s * 512);
            }
        }

        #pragma unroll
        for (int kk = 0; kk < 32; kk += 8) {
            uint32_t ahi[2][4], alo[2][4];
            #pragma unroll
            for (int mt = 0; mt < 2; mt++) {
                const int row = warp_m * 32 + mt * 16 + gid;
                const uint32_t* p0 = Ah + row * SA + kk + tig;
                const uint32_t* p1 = Ah + (row + 8) * SA + kk + tig;
                ahi[mt][0] = p0[0]; ahi[mt][1] = p1[0];
                ahi[mt][2] = p0[4]; ahi[mt][3] = p1[4];
                const uint32_t* q0 = Al + row * SA + kk + tig;
                const uint32_t* q1 = Al + (row + 8) * SA + kk + tig;
                alo[mt][0] = q0[0]; alo[mt][1] = q1[0];
                alo[mt][2] = q0[4]; alo[mt][3] = q1[4];
            }
            #pragma unroll
            for (int nt = 0; nt < 4; nt++) {
                const int col = warp_n * 32 + nt * 8 + gid;
                const uint32_t bh0 = Bh[col * SB + kk + tig];
                const uint32_t bh1 = Bh[col * SB + kk + tig + 4];
                const uint32_t bl0 = Bl[col * SB + kk + tig];
                const uint32_t bl1 = Bl[col * SB + kk + tig + 4];
                #pragma unroll
                for (int mt = 0; mt < 2; mt++) {
                    mma_tf32(acc[mt][nt], ahi[mt], bh0, bh1);
                    mma_tf32(acc[mt][nt], ahi[mt], bl0, bl1);
                    mma_tf32(acc[mt][nt], alo[mt], bh0, bh1);
                }
            }
        }

        if (pf) {
            uint32_t* nAh = sm + (cur ^ 1) * BUF_W;
            #pragma unroll
            for (int s = 0; s < 2; s++) {
                int p = tid + s * 512;
                tl_sts<MA, SA>(pva[s], nAh, nAh + TA_W, p);
                tl_sts<MB, SB>(pvb[s], nAh + 2 * TA_W, nAh + 2 * TA_W + TB_W, p);
            }
        }
        __syncthreads();
    }

    // ---- epilogue: direct global stores (float2, 8B-aligned) ----
    #pragma unroll
    for (int mt = 0; mt < 2; mt++) {
        const int r0i = m0 + warp_m * 32 + mt * 16 + gid;
        const int r1i = r0i + 8;
        const float b0f = bias ? bias[r0i] : 0.f;
        const float b1f = bias ? bias[r1i] : 0.f;
        #pragma unroll
        for (int nt = 0; nt < 4; nt++) {
            const int cc = n0 + warp_n * 32 + nt * 8 + 2 * tig;
            float v0 = acc[mt][nt][0] * alpha + b0f;
            float v1 = acc[mt][nt][1] * alpha + b0f;
            float v2 = acc[mt][nt][2] * alpha + b1f;
            float v3 = acc[mt][nt][3] * alpha + b1f;
            const size_t o0 = (size_t)r0i * ldc + cc;
            const size_t o1 = (size_t)r1i * ldc + cc;
            if (Res) {
                float2 r0v = *(const float2*)(Res + o0);
                float2 r1v = *(const float2*)(Res + o1);
                v0 += r0v.x; v1 += r0v.y; v2 += r1v.x; v3 += r1v.y;
            }
            *(float2*)(C + o0) = make_float2(v0, v1);
            *(float2*)(C + o1) = make_float2(v2, v3);
        }
    }
}

// ---------------- GroupNorm: one block per (batch, group) ----------------
__global__ void __launch_bounds__(256) groupnorm_kernel(
    const float* __restrict__ x, const float* __restrict__ gamma,
    const float* __restrict__ beta, float* __restrict__ hn)
{
    const int bg = blockIdx.x;
    const int b = bg / G_GROUPS, g = bg % G_GROUPS;
    const size_t base = ((size_t)b * C_DIM + (size_t)g * CPG) * N_POS;
    const float* xp = x + base;
    float* hp = hn + base;
    const int tid = threadIdx.x;
    const int NEL = CPG * N_POS;

    float s = 0.f, s2 = 0.f;
    for (int i = tid; i < NEL; i += 256) {
        float v = xp[i];
        s += v; s2 += v * v;
    }
    __shared__ float sh0[256], sh1[256];
    sh0[tid] = s; sh1[tid] = s2;
    __syncthreads();
    for (int o = 128; o > 0; o >>= 1) {
        if (tid < o) { sh0[tid] += sh0[tid + o]; sh1[tid] += sh1[tid + o]; }
        __syncthreads();
    }
    const float mean = sh0[0] * (1.0f / NEL);
    const float var  = sh1[0] * (1.0f / NEL) - mean * mean;
    const float rstd = rsqrtf(var + EPS);

    for (int i = tid; i < NEL; i += 256) {
        const int cc = i >> 12;
        const int c  = g * CPG + cc;
        hp[i] = (xp[i] - mean) * rstd * gamma[c] + beta[c];
    }
}

// ---------------- row softmax (rows of length 4096) ----------------
__global__ void __launch_bounds__(256) softmax_kernel(float* __restrict__ attn)
{
    float* p = attn + (size_t)blockIdx.x * N_POS;
    const int tid = threadIdx.x;
    float v[16];
    float mx = -1e30f;
    #pragma unroll
    for (int i = 0; i < 16; i++) {
        v[i] = p[tid + i * 256];
        mx = fmaxf(mx, v[i]);
    }
    __shared__ float sh[256];
    sh[tid] = mx;
    __syncthreads();
    for (int o = 128; o > 0; o >>= 1) {
        if (tid < o) sh[tid] = fmaxf(sh[tid], sh[tid + o]);
        __syncthreads();
    }
    mx = sh[0];
    __syncthreads();

    float s = 0.f;
    #pragma unroll
    for (int i = 0; i < 16; i++) {
        v[i] = __expf(v[i] - mx);
        s += v[i];
    }
    sh[tid] = s;
    __syncthreads();
    for (int o = 128; o > 0; o >>= 1) {
        if (tid < o) sh[tid] += sh[tid + o];
        __syncthreads();
    }
    const float inv = 1.0f / sh[0];
    #pragma unroll
    for (int i = 0; i < 16; i++)
        p[tid + i * 256] = v[i] * inv;
}

// ---------------- tiled transpose: out2[b][m][n] = attn[b][n][m] ----------------
__global__ void __launch_bounds__(256) transpose_kernel(
    const float* __restrict__ attn, float* __restrict__ out2)
{
    __shared__ float tile[32][33];
    const int b  = blockIdx.z;
    const int n0 = blockIdx.x * 32;
    const int m0 = blockIdx.y * 32;
    const float* src = attn + (size_t)b * N_POS * N_POS;
    float*       dst = out2 + (size_t)b * N_POS * N_POS;
    const int tx = threadIdx.x;
    const int ty = threadIdx.y;
    #pragma unroll
    for (int j = 0; j < 4; j++)
        tile[ty + j * 8][tx] = src[(size_t)(n0 + ty + j * 8) * N_POS + (m0 + tx)];
    __syncthreads();
    #pragma unroll
    for (int j = 0; j < 4; j++)
        dst[(size_t)(m0 + ty + j * 8) * N_POS + (n0 + tx)] = tile[tx][ty + j * 8];
}

// ---------------- launch ----------------
static inline int smem_bytes(int ma, int mb) {
    int sa = ma ? 36 : 33, sb = mb ? 36 : 33;
    return 2 * (2 * 128 * sa + 2 * 128 * sb) * 4;
}

extern "C" void kernel_launch(void* const* d_in, const int* in_sizes, int n_in,
                              void* d_out, int out_size)
{
    const float* x     = (const float*)d_in[0];
    const float* gamma = (const float*)d_in[1];
    const float* beta  = (const float*)d_in[2];
    const float* wq    = (const float*)d_in[3];
    const float* bq    = (const float*)d_in[4];
    const float* wk    = (const float*)d_in[5];
    const float* bk    = (const float*)d_in[6];
    const float* wv    = (const float*)d_in[7];
    const float* bv    = (const float*)d_in[8];
    const float* wp    = (const float*)d_in[9];
    const float* bp    = (const float*)d_in[10];

    float* out1 = (float*)d_out;
    float* out2 = out1 + (size_t)B_DIM * C_DIM * N_POS;

    float *hn, *q, *k, *v, *hv, *attn;
    cudaGetSymbolAddress((void**)&hn,   g_hn);
    cudaGetSymbolAddress((void**)&q,    g_q);
    cudaGetSymbolAddress((void**)&k,    g_k);
    cudaGetSymbolAddress((void**)&v,    g_v);
    cudaGetSymbolAddress((void**)&hv,   g_hv);
    cudaGetSymbolAddress((void**)&attn, g_attn);

    const int sm10 = smem_bytes(1, 0);
    const int sm00 = smem_bytes(0, 0);
    const int sm11 = smem_bytes(1, 1);
    cudaFuncSetAttribute(gemm_tc<1,0>, cudaFuncAttributeMaxDynamicSharedMemorySize, sm10);
    cudaFuncSetAttribute(gemm_tc<0,0>, cudaFuncAttributeMaxDynamicSharedMemorySize, sm00);
    cudaFuncSetAttribute(gemm_tc<1,1>, cudaFuncAttributeMaxDynamicSharedMemorySize, sm11);

    const size_t CN  = (size_t)C_DIM * N_POS;
    const size_t NN2 = (size_t)N_POS * N_POS;
    const float scale = 0.0625f;                // 256^-0.5

    // 1) GroupNorm -> hn
    groupnorm_kernel<<<B_DIM * G_GROUPS, 256>>>(x, gamma, beta, hn);

    // 2) q/k/v[o,n] = sum_c W[o,c] hn[c,n] + b : A=W [m][k] (T), B=hn [k][n] (D)
    dim3 gp(N_POS / 128, C_DIM / 128, B_DIM);   // (32, 2, 2)
    gemm_tc<1,0><<<gp, 512, sm10>>>(wq, hn, q, C_DIM, C_DIM, N_POS, N_POS,
                                    bq, nullptr, 1.f, 0, CN, CN);
    gemm_tc<1,0><<<gp, 512, sm10>>>(wk, hn, k, C_DIM, C_DIM, N_POS, N_POS,
                                    bk, nullptr, 1.f, 0, CN, CN);
    gemm_tc<1,0><<<gp, 512, sm10>>>(wv, hn, v, C_DIM, C_DIM, N_POS, N_POS,
                                    bv, nullptr, 1.f, 0, CN, CN);

    // 3) s[n,m] = scale * sum_c q[c,n] k[c,m] : A=q [k][m] (D), B=k [k][n] (D)
    dim3 gqk(N_POS / 128, N_POS / 128, B_DIM);  // (32, 32, 2)
    gemm_tc<0,0><<<gqk, 512, sm00>>>(q, k, attn, C_DIM, N_POS, N_POS, N_POS,
                                     nullptr, nullptr, scale, CN, CN, NN2);

    // 4) row softmax
    softmax_kernel<<<B_DIM * N_POS, 256>>>(attn);

    // 5) hv[c,n] = sum_m v[c,m] p[n,m] : A=v [m][k] (T), B=p [n][k] (T)
    gemm_tc<1,1><<<gp, 512, sm11>>>(v, attn, hv, N_POS, N_POS, N_POS, N_POS,
                                    nullptr, nullptr, 1.f, CN, NN2, CN);

    // 6) out1 = x + wp*hv + bp : A=wp (T), B=hv [k][n] (D)
    gemm_tc<1,0><<<gp, 512, sm10>>>(wp, hv, out1, C_DIM, C_DIM, N_POS, N_POS,
                                    bp, x, 1.f, 0, CN, CN);

    // 7) out2[b,m,n] = attn[b,n,m]
    transpose_kernel<<<dim3(N_POS / 32, N_POS / 32, B_DIM), dim3(32, 8)>>>(attn, out2);
}

// round 7
// speedup vs baseline: 1.9233x; 1.7280x over previous
#include <cuda_runtime.h>
#include <cuda_fp16.h>
#include <math.h>
#include <stdint.h>

#define B_DIM 2
#define C_DIM 256
#define N_POS 4096
#define G_GROUPS 32
#define CPG 8
#define EPS 1e-6f

// ---------------- scratch (device globals; no allocation allowed) ----------------
__device__ float g_hn [(size_t)B_DIM * C_DIM * N_POS];
__device__ float g_q  [(size_t)B_DIM * C_DIM * N_POS];
__device__ float g_k  [(size_t)B_DIM * C_DIM * N_POS];
__device__ float g_v  [(size_t)B_DIM * C_DIM * N_POS];
__device__ float g_hv [(size_t)B_DIM * C_DIM * N_POS];
__device__ float g_attn[(size_t)B_DIM * N_POS * N_POS];   // raw logits, 128 MB
__device__ float g_rmax[(size_t)B_DIM * N_POS];
__device__ float g_rinv[(size_t)B_DIM * N_POS];

// =================== smem tile geometry ===================
// Tile: 128 rows x 32 k-elems fp16, stored as 16 b32 words/row, row stride 20 words
// (20/4 = 5 odd -> conflict-free ldmatrix phases; rows 16B-aligned).
#define TS 20
#define TILEW (128 * TS)            // 2560 words per tile
#define BUFW  (4 * TILEW)           // Ahi, Alo, Bhi, Blo
#define SMEM_GEMM (2 * BUFW * 4)    // 81920 bytes, double buffered

// =================== PTX helpers (plain sm_80+; compiles for sm_103 target) ===================
__device__ __forceinline__ uint32_t smem_u32(const void* p) {
    uint32_t a;
    asm("{ .reg .u64 t; cvta.to.shared.u64 t, %1; cvt.u32.u64 %0, t; }"
        : "=r"(a) : "l"(p));
    return a;
}

__device__ __forceinline__ void ldsm4(uint32_t* r, uint32_t addr) {
    asm volatile("ldmatrix.sync.aligned.m8n8.x4.shared.b16 {%0,%1,%2,%3}, [%4];"
                 : "=r"(r[0]), "=r"(r[1]), "=r"(r[2]), "=r"(r[3]) : "r"(addr));
}

__device__ __forceinline__ void mma_fp16(float* c, const uint32_t* a,
                                         uint32_t b0, uint32_t b1) {
    asm volatile(
        "mma.sync.aligned.m16n8k16.row.col.f32.f16.f16.f32 "
        "{%0,%1,%2,%3}, {%4,%5,%6,%7}, {%8,%9}, {%0,%1,%2,%3};"
        : "+f"(c[0]), "+f"(c[1]), "+f"(c[2]), "+f"(c[3])
        : "r"(a[0]), "r"(a[1]), "r"(a[2]), "r"(a[3]), "r"(b0), "r"(b1));
}

// fp16 split: x = hi + lo, each fp16 -> ~22 mantissa bits combined
__device__ __forceinline__ void split4(const float* x, uint2& hi, uint2& lo) {
    uint32_t hs[4], ls[4];
    #pragma unroll
    for (int j = 0; j < 4; j++) {
        __half h = __float2half_rn(x[j]);
        __half l = __float2half_rn(x[j] - __half2float(h));
        hs[j] = __half_as_ushort(h);
        ls[j] = __half_as_ushort(l);
    }
    hi = make_uint2(hs[0] | (hs[1] << 16), hs[2] | (hs[3] << 16));
    lo = make_uint2(ls[0] | (ls[1] << 16), ls[2] | (ls[3] << 16));
}

// Per-thread staging: 2 units, unit = (row ur, k-quad kq) of 4 floats.
//  MODE=1 ("T"): src row-major [r][k] -> one float4
//  MODE=0 ("D"): src [k][r]           -> 4 stride-ld scalars (coalesced across lanes)
template<int MODE>
__device__ __forceinline__ void ldg2(const float* __restrict__ src, int ld,
                                     int r0, int k0, int ur, int ukq, float x[2][4]) {
    #pragma unroll
    for (int u = 0; u < 2; u++) {
        const int kq = ukq + u * 4;
        if (MODE) {
            float4 v = *(const float4*)(src + (size_t)(r0 + ur) * ld + k0 + 4 * kq);
            x[u][0] = v.x; x[u][1] = v.y; x[u][2] = v.z; x[u][3] = v.w;
        } else {
            const float* p = src + (size_t)(k0 + 4 * kq) * ld + r0 + ur;
            x[u][0] = p[0];
            x[u][1] = p[(size_t)ld];
            x[u][2] = p[2 * (size_t)ld];
            x[u][3] = p[3 * (size_t)ld];
        }
    }
}

__device__ __forceinline__ void sts2(uint32_t* __restrict__ buf, int ur, int ukq,
                                     float xa[2][4], float xb[2][4]) {
    #pragma unroll
    for (int u = 0; u < 2; u++) {
        const int w = ur * TS + 2 * (ukq + u * 4);
        uint2 hi, lo;
        split4(xa[u], hi, lo);
        *(uint2*)(buf + w)             = hi;
        *(uint2*)(buf + TILEW + w)     = lo;
        split4(xb[u], hi, lo);
        *(uint2*)(buf + 2 * TILEW + w) = hi;
        *(uint2*)(buf + 3 * TILEW + w) = lo;
    }
}

// =================== fp16-split HMMA GEMM ===================
// C[m,n] = alpha * sum_k A[m,k]*B[n,k] (+bias[m]) (+res[m,n])
// CTA 128x128, K-chunk 32, 512 threads (16 warps, 4x4 grid of 32x32 warp tiles),
// double-buffered smem, ldmatrix.x4 fragment loads, 3 MMAs per k16 (hh + hl + lh).
template<int MA, int MB>
__global__ void __launch_bounds__(512) gemm_tc(
    const float* __restrict__ A, const float* __restrict__ B, float* __restrict__ C,
    int K, int lda, int ldb, int ldc,
    const float* __restrict__ bias, const float* __restrict__ res, float alpha,
    size_t strA, size_t strB, size_t strC)
{
    extern __shared__ __align__(16) uint32_t sm[];

    const int tid = threadIdx.x;
    const int lane = tid & 31, wid = tid >> 5;
    const int warp_m = wid & 3, warp_n = wid >> 2;
    const int gid = lane >> 2, tig = lane & 3;

    const int bz = blockIdx.z;
    A += strA * bz;
    B += strB * bz;
    C += strC * bz;
    const float* Res = res ? res + strC * bz : nullptr;
    const int n0 = blockIdx.x * 128, m0 = blockIdx.y * 128;

    // staging coords (2 units/thread: same row, kq and kq+4)
    const int ur = tid & 127;
    const int ukq = tid >> 7;

    // ldmatrix lane addressing: lanes 0-15 -> rows 0-15 (first 16B col-block),
    // lanes 16-31 -> rows 0-15 (+16B). One x4 = full m16k16 fragment.
    const uint32_t sb = smem_u32(sm);
    const int lrow = lane & 15;
    const int lhalf = (lane >> 4) & 1;
    const uint32_t aoff = (uint32_t)((warp_m * 32 + lrow) * TS) * 4 + lhalf * 16;
    const uint32_t boff = (uint32_t)((warp_n * 32 + lrow) * TS) * 4 + lhalf * 16;

    float acc[2][4][4];
    #pragma unroll
    for (int i = 0; i < 2; i++)
        #pragma unroll
        for (int j = 0; j < 4; j++)
            #pragma unroll
            for (int t = 0; t < 4; t++) acc[i][j][t] = 0.f;

    // stage chunk 0 -> buffer 0
    {
        float xa[2][4], xb[2][4];
        ldg2<MA>(A, lda, m0, 0, ur, ukq, xa);
        ldg2<MB>(B, ldb, n0, 0, ur, ukq, xb);
        sts2(sm, ur, ukq, xa, xb);
    }
    __syncthreads();

    const int nc = K >> 5;
    for (int c = 0; c < nc; c++) {
        const int cur = c & 1;
        float xa[2][4], xb[2][4];
        const bool pf = (c + 1) < nc;
        if (pf) {
            const int k0 = (c + 1) << 5;
            ldg2<MA>(A, lda, m0, k0, ur, ukq, xa);
            ldg2<MB>(B, ldb, n0, k0, ur, ukq, xb);
        }

        const uint32_t base = sb + (uint32_t)cur * (BUFW * 4);
        #pragma unroll
        for (int s = 0; s < 2; s++) {
            uint32_t ah[2][4], al[2][4], bh[2][4], bl[2][4];
            #pragma unroll
            for (int mt = 0; mt < 2; mt++) {
                ldsm4(ah[mt], base + aoff + mt * (16 * TS * 4) + s * 32);
                ldsm4(al[mt], base + TILEW * 4 + aoff + mt * (16 * TS * 4) + s * 32);
            }
            #pragma unroll
            for (int np = 0; np < 2; np++) {
                ldsm4(bh[np], base + 2 * TILEW * 4 + boff + np * (16 * TS * 4) + s * 32);
                ldsm4(bl[np], base + 3 * TILEW * 4 + boff + np * (16 * TS * 4) + s * 32);
            }
            #pragma unroll
            for (int np = 0; np < 2; np++)
                #pragma unroll
                for (int h = 0; h < 2; h++) {
                    const int nt = np * 2 + h;
                    const uint32_t B0h = bh[np][h], B1h = bh[np][2 + h];
                    const uint32_t B0l = bl[np][h], B1l = bl[np][2 + h];
                    #pragma unroll
                    for (int mt = 0; mt < 2; mt++) {
                        mma_fp16(acc[mt][nt], ah[mt], B0h, B1h);
                        mma_fp16(acc[mt][nt], ah[mt], B0l, B1l);
                        mma_fp16(acc[mt][nt], al[mt], B0h, B1h);
                    }
                }
        }

        if (pf) sts2(sm + (cur ^ 1) * BUFW, ur, ukq, xa, xb);
        __syncthreads();
    }

    // ---- epilogue: direct global stores (float2) ----
    #pragma unroll
    for (int mt = 0; mt < 2; mt++) {
        const int r0i = m0 + warp_m * 32 + mt * 16 + gid;
        const int r1i = r0i + 8;
        const float b0f = bias ? bias[r0i] : 0.f;
        const float b1f = bias ? bias[r1i] : 0.f;
        #pragma unroll
        for (int nt = 0; nt < 4; nt++) {
            const int cc = n0 + warp_n * 32 + nt * 8 + 2 * tig;
            float v0 = acc[mt][nt][0] * alpha + b0f;
            float v1 = acc[mt][nt][1] * alpha + b0f;
            float v2 = acc[mt][nt][2] * alpha + b1f;
            float v3 = acc[mt][nt][3] * alpha + b1f;
            const size_t o0 = (size_t)r0i * ldc + cc;
            const size_t o1 = (size_t)r1i * ldc + cc;
            if (Res) {
                float2 r0v = *(const float2*)(Res + o0);
                float2 r1v = *(const float2*)(Res + o1);
                v0 += r0v.x; v1 += r0v.y; v2 += r1v.x; v3 += r1v.y;
            }
            *(float2*)(C + o0) = make_float2(v0, v1);
            *(float2*)(C + o1) = make_float2(v2, v3);
        }
    }
}

// ---------------- GroupNorm: one block per (batch, group) ----------------
__global__ void __launch_bounds__(256) groupnorm_kernel(
    const float* __restrict__ x, const float* __restrict__ gamma,
    const float* __restrict__ beta, float* __restrict__ hn)
{
    const int bg = blockIdx.x;
    const int b = bg / G_GROUPS, g = bg % G_GROUPS;
    const size_t base = ((size_t)b * C_DIM + (size_t)g * CPG) * N_POS;
    const float* xp = x + base;
    float* hp = hn + base;
    const int tid = threadIdx.x;
    const int NEL = CPG * N_POS;

    float s = 0.f, s2 = 0.f;
    for (int i = tid; i < NEL; i += 256) {
        float v = xp[i];
        s += v; s2 += v * v;
    }
    __shared__ float sh0[256], sh1[256];
    sh0[tid] = s; sh1[tid] = s2;
    __syncthreads();
    for (int o = 128; o > 0; o >>= 1) {
        if (tid < o) { sh0[tid] += sh0[tid + o]; sh1[tid] += sh1[tid + o]; }
        __syncthreads();
    }
    const float mean = sh0[0] * (1.0f / NEL);
    const float var  = sh1[0] * (1.0f / NEL) - mean * mean;
    const float rstd = rsqrtf(var + EPS);

    for (int i = tid; i < NEL; i += 256) {
        const int cc = i >> 12;
        const int c  = g * CPG + cc;
        hp[i] = (xp[i] - mean) * rstd * gamma[c] + beta[c];
    }
}

// ---------------- row stats: max + 1/sum(exp) per logit row ----------------
__global__ void __launch_bounds__(256) stats_kernel(
    const float* __restrict__ attn, float* __restrict__ rmax, float* __restrict__ rinv)
{
    const size_t row = blockIdx.x;
    const float* p = attn + row * N_POS;
    const int tid = threadIdx.x;
    float v[16];
    float mx = -1e30f;
    #pragma unroll
    for (int i = 0; i < 16; i++) {
        v[i] = p[tid + i * 256];
        mx = fmaxf(mx, v[i]);
    }
    __shared__ float sh[256];
    sh[tid] = mx;
    __syncthreads();
    for (int o = 128; o > 0; o >>= 1) {
        if (tid < o) sh[tid] = fmaxf(sh[tid], sh[tid + o]);
        __syncthreads();
    }
    mx = sh[0];
    __syncthreads();
    float s = 0.f;
    #pragma unroll
    for (int i = 0; i < 16; i++) s += __expf(v[i] - mx);
    sh[tid] = s;
    __syncthreads();
    for (int o = 128; o > 0; o >>= 1) {
        if (tid < o) sh[tid] += sh[tid + o];
        __syncthreads();
    }
    if (tid == 0) {
        rmax[row] = mx;
        rinv[row] = 1.0f / sh[0];
    }
}

// ---------------- normalize + transpose: out2[b][m][n] = softmax(attn)[b][n][m] ----------------
__global__ void __launch_bounds__(256) transpose_norm_kernel(
    const float* __restrict__ attn, const float* __restrict__ rmax,
    const float* __restrict__ rinv, float* __restrict__ out2)
{
    __shared__ float tile[32][33];
    const int bz = blockIdx.z;
    const int n0 = blockIdx.x * 32;
    const int m0 = blockIdx.y * 32;
    const float* src = attn + (size_t)bz * N_POS * N_POS;
    float*       dst = out2 + (size_t)bz * N_POS * N_POS;
    const int tx = threadIdx.x;
    const int ty = threadIdx.y;
    #pragma unroll
    for (int j = 0; j < 4; j++) {
        const int n = n0 + ty + j * 8;
        const float mx = rmax[bz * N_POS + n];
        const float iv = rinv[bz * N_POS + n];
        const float raw = src[(size_t)n * N_POS + (m0 + tx)];
        tile[ty + j * 8][tx] = __expf(raw - mx) * iv;
    }
    __syncthreads();
    #pragma unroll
    for (int j = 0; j < 4; j++)
        dst[(size_t)(m0 + ty + j * 8) * N_POS + (n0 + tx)] = tile[tx][ty + j * 8];
}

// ---------------- launch ----------------
extern "C" void kernel_launch(void* const* d_in, const int* in_sizes, int n_in,
                              void* d_out, int out_size)
{
    const float* x     = (const float*)d_in[0];
    const float* gamma = (const float*)d_in[1];
    const float* beta  = (const float*)d_in[2];
    const float* wq    = (const float*)d_in[3];
    const float* bq    = (const float*)d_in[4];
    const float* wk    = (const float*)d_in[5];
    const float* bk    = (const float*)d_in[6];
    const float* wv    = (const float*)d_in[7];
    const float* bv    = (const float*)d_in[8];
    const float* wp    = (const float*)d_in[9];
    const float* bp    = (const float*)d_in[10];

    float* out1 = (float*)d_out;
    float* out2 = out1 + (size_t)B_DIM * C_DIM * N_POS;

    float *hn, *q, *k, *v, *hv, *attn, *rmax, *rinv;
    cudaGetSymbolAddress((void**)&hn,   g_hn);
    cudaGetSymbolAddress((void**)&q,    g_q);
    cudaGetSymbolAddress((void**)&k,    g_k);
    cudaGetSymbolAddress((void**)&v,    g_v);
    cudaGetSymbolAddress((void**)&hv,   g_hv);
    cudaGetSymbolAddress((void**)&attn, g_attn);
    cudaGetSymbolAddress((void**)&rmax, g_rmax);
    cudaGetSymbolAddress((void**)&rinv, g_rinv);

    cudaFuncSetAttribute(gemm_tc<1,0>, cudaFuncAttributeMaxDynamicSharedMemorySize, SMEM_GEMM);
    cudaFuncSetAttribute(gemm_tc<0,0>, cudaFuncAttributeMaxDynamicSharedMemorySize, SMEM_GEMM);

    const size_t CN  = (size_t)C_DIM * N_POS;
    const size_t NN2 = (size_t)N_POS * N_POS;
    const float scale = 0.0625f;                // 256^-0.5

    // 1) GroupNorm -> hn
    groupnorm_kernel<<<B_DIM * G_GROUPS, 256>>>(x, gamma, beta, hn);

    // 2) q/k/v[o,n] = sum_c W[o,c] hn[c,n] + b : A=W (T, ld=256), B=hn (D, ld=4096)
    dim3 gp(N_POS / 128, C_DIM / 128, B_DIM);   // (32, 2, 2)
    gemm_tc<1,0><<<gp, 512, SMEM_GEMM>>>(wq, hn, q, C_DIM, C_DIM, N_POS, N_POS,
                                         bq, nullptr, 1.f, 0, CN, CN);
    gemm_tc<1,0><<<gp, 512, SMEM_GEMM>>>(wk, hn, k, C_DIM, C_DIM, N_POS, N_POS,
                                         bk, nullptr, 1.f, 0, CN, CN);
    gemm_tc<1,0><<<gp, 512, SMEM_GEMM>>>(wv, hn, v, C_DIM, C_DIM, N_POS, N_POS,
                                         bv, nullptr, 1.f, 0, CN, CN);

    // 3) raw logits s[n,m] = scale * sum_c q[c,n] k[c,m] : A=q (D), B=k (D)
    dim3 gqk(N_POS / 128, N_POS / 128, B_DIM);  // (32, 32, 2)
    gemm_tc<0,0><<<gqk, 512, SMEM_GEMM>>>(q, k, attn, C_DIM, N_POS, N_POS, N_POS,
                                          nullptr, nullptr, scale, CN, CN, NN2);

    // 4) row stats (max, 1/sumexp)
    stats_kernel<<<B_DIM * N_POS, 256>>>(attn, rmax, rinv);

    // 5) out2[b,m,n] = softmax(attn)[b,n,m]  (normalize fused into transpose)
    transpose_norm_kernel<<<dim3(N_POS / 32, N_POS / 32, B_DIM), dim3(32, 8)>>>(
        attn, rmax, rinv, out2);

    // 6) hv[c,n] = sum_m v[c,m] P[n,m] : A=v (T, ld=4096), B=out2 (D: B[n][m]=out2[m][n])
    gemm_tc<1,0><<<gp, 512, SMEM_GEMM>>>(v, out2, hv, N_POS, N_POS, N_POS, N_POS,
                                         nullptr, nullptr, 1.f, CN, NN2, CN);

    // 7) out1 = x + wp*hv + bp : A=wp (T), B=hv (D)
    gemm_tc<1,0><<<gp, 512, SMEM_GEMM>>>(wp, hv, out1, C_DIM, C_DIM, N_POS, N_POS,
                                         bp, x, 1.f, 0, CN, CN);
}

// round 8
// speedup vs baseline: 2.5736x; 1.3381x over previous
#include <cuda_runtime.h>
#include <cuda_fp16.h>
#include <math.h>
#include <stdint.h>

#define B_DIM 2
#define C_DIM 256
#define N_POS 4096
#define G_GROUPS 32
#define CPG 8
#define EPS 1e-6f

// ---------------- scratch (device globals; no allocation allowed) ----------------
__device__ __align__(16) uint32_t g_hnT[(size_t)B_DIM * N_POS * C_DIM];  // pk(hi|lo) [b][n][c]
__device__ __align__(16) uint32_t g_qT [(size_t)B_DIM * N_POS * C_DIM];  // pk [b][n][c]
__device__ __align__(16) uint32_t g_kT [(size_t)B_DIM * N_POS * C_DIM];  // pk [b][n][c]
__device__ __align__(16) uint32_t g_v16[(size_t)B_DIM * C_DIM * N_POS];  // pk [b][c][m]
__device__ __align__(16) float    g_attn[(size_t)B_DIM * N_POS * N_POS]; // raw logits
__device__ __align__(16) __half   g_p16[(size_t)B_DIM * N_POS * N_POS];  // softmax fp16 [b][n][m]
__device__ __align__(16) float    g_pt0[(size_t)B_DIM * C_DIM * N_POS];
__device__ __align__(16) float    g_pt1[(size_t)B_DIM * C_DIM * N_POS];
__device__ __align__(16) float    g_hv [(size_t)B_DIM * C_DIM * N_POS];
__device__ float g_rmax[(size_t)B_DIM * N_POS];
__device__ float g_rinv[(size_t)B_DIM * N_POS];

// =================== smem tile geometry ===================
// A tile 128 rows x 32 k (fp16 -> 16 words/row), B tile 64 rows x 32 k.
// Row stride TS=20 words (20/4=5 odd -> conflict-free ldmatrix phases).
#define TS 20
#define TAW (128 * TS)
#define TBW (64 * TS)

// =================== PTX helpers ===================
__device__ __forceinline__ uint32_t smem_u32(const void* p) {
    uint32_t a;
    asm("{ .reg .u64 t; cvta.to.shared.u64 t, %1; cvt.u32.u64 %0, t; }"
        : "=r"(a) : "l"(p));
    return a;
}
__device__ __forceinline__ void ldsm4(uint32_t* r, uint32_t addr) {
    asm volatile("ldmatrix.sync.aligned.m8n8.x4.shared.b16 {%0,%1,%2,%3}, [%4];"
                 : "=r"(r[0]), "=r"(r[1]), "=r"(r[2]), "=r"(r[3]) : "r"(addr));
}
__device__ __forceinline__ void mma_fp16(float* c, const uint32_t* a,
                                         uint32_t b0, uint32_t b1) {
    asm volatile(
        "mma.sync.aligned.m16n8k16.row.col.f32.f16.f16.f32 "
        "{%0,%1,%2,%3}, {%4,%5,%6,%7}, {%8,%9}, {%0,%1,%2,%3};"
        : "+f"(c[0]), "+f"(c[1]), "+f"(c[2]), "+f"(c[3])
        : "r"(a[0]), "r"(a[1]), "r"(a[2]), "r"(a[3]), "r"(b0), "r"(b1));
}

// packed fp16 split word: low16 = hi part, high16 = lo part
__device__ __forceinline__ uint32_t pack_pk(float x) {
    __half h = __float2half_rn(x);
    __half l = __float2half_rn(x - __half2float(h));
    return (uint32_t)__half_as_ushort(h) | ((uint32_t)__half_as_ushort(l) << 16);
}
__device__ __forceinline__ void split2(float x0, float x1, uint32_t& h, uint32_t& l) {
    __half h0 = __float2half_rn(x0), h1 = __float2half_rn(x1);
    __half l0 = __float2half_rn(x0 - __half2float(h0));
    __half l1 = __float2half_rn(x1 - __half2float(h1));
    h = (uint32_t)__half_as_ushort(h0) | ((uint32_t)__half_as_ushort(h1) << 16);
    l = (uint32_t)__half_as_ushort(l0) | ((uint32_t)__half_as_ushort(l1) << 16);
}

// =================== operand staging ===================
// formats: 0 = fp32 row-major [r][k] ("T"), 1 = fp32 [k][r] ("D"),
//          2 = packed-fp16 row-major [r][k], 3 = plain fp16 row-major [r][k]
template<int F, int ROWS>
__device__ __forceinline__ void qmap(int qi, int& r, int& kq) {
    if (F == 1) { r = qi & (ROWS - 1); kq = qi / ROWS; }
    else        { kq = qi & 7;         r = qi >> 3; }
}
template<int F, int ROWS>
__device__ __forceinline__ uint4 op_ldg(const void* src, int ld, int r0, int k0, int qi) {
    int r, kq;
    qmap<F, ROWS>(qi, r, kq);
    uint4 out;
    if (F == 0) {
        float4 v = *(const float4*)((const float*)src + (size_t)(r0 + r) * ld + k0 + 4 * kq);
        out = *(uint4*)&v;
    } else if (F == 1) {
        const float* p = (const float*)src + (size_t)(k0 + 4 * kq) * ld + r0 + r;
        float4 v = make_float4(p[0], p[(size_t)ld], p[2 * (size_t)ld], p[3 * (size_t)ld]);
        out = *(uint4*)&v;
    } else if (F == 2) {
        out = *(const uint4*)((const uint32_t*)src + (size_t)(r0 + r) * ld + k0 + 4 * kq);
    } else {
        uint2 v = *(const uint2*)((const __half*)src + (size_t)(r0 + r) * ld + k0 + 4 * kq);
        out = make_uint4(v.x, v.y, 0u, 0u);
    }
    return out;
}
template<int F, int ROWS>
__device__ __forceinline__ void op_sts(uint4 raw, uint32_t* __restrict__ hi,
                                       uint32_t* __restrict__ lo, int qi) {
    int r, kq;
    qmap<F, ROWS>(qi, r, kq);
    const int w = r * TS + 2 * kq;
    if (F == 0 || F == 1) {
        const float* x = (const float*)&raw;
        uint32_t h0, l0, h1, l1;
        split2(x[0], x[1], h0, l0);
        split2(x[2], x[3], h1, l1);
        *(uint2*)(hi + w) = make_uint2(h0, h1);
        *(uint2*)(lo + w) = make_uint2(l0, l1);
    } else if (F == 2) {
        *(uint2*)(hi + w) = make_uint2(__byte_perm(raw.x, raw.y, 0x5410),
                                       __byte_perm(raw.z, raw.w, 0x5410));
        *(uint2*)(lo + w) = make_uint2(__byte_perm(raw.x, raw.y, 0x7632),
                                       __byte_perm(raw.z, raw.w, 0x7632));
    } else {
        *(uint2*)(hi + w) = make_uint2(raw.x, raw.y);
    }
}

// =================== fp16-split HMMA GEMM ===================
// C[m,n] = alpha * sum_k A[m,k]*B[n,k]; CTA tile 128(M) x 64(N), K-chunk 32,
// 256 threads (8 warps, 4m x 2n grid of 32x32 warp tiles), double-buffered smem.
// SPLITB: B has a lo tile (3 MMAs/k16) vs single fp16 B (2 MMAs/k16).
// EPI: 0 = fp32 store (alpha, bias?, res?), 1 = packed transposed store ([n][c]),
//      2 = packed direct store ([c][n]).
// KS: gridDim.y = 4 encodes (ksplit, mtile); split sp writes to C2.
template<int AF, int BF, int SPLITB, int EPI, int KS>
__global__ void __launch_bounds__(256, 2) gemm_tc(
    const void* __restrict__ Av, const void* __restrict__ Bv, void* __restrict__ Cv,
    int K, int lda, int ldb, int ldc,
    const float* __restrict__ bias, const float* __restrict__ res,
    float alpha, size_t strA, size_t strB, size_t strC, float* __restrict__ C2)
{
    constexpr int BUFW = 2 * TAW + (SPLITB ? 2 * TBW : TBW);
    extern __shared__ __align__(16) uint32_t smw[];

    const int tid = threadIdx.x;
    const int lane = tid & 31, wid = tid >> 5;
    const int warp_m = wid & 3, warp_n = wid >> 2;   // 4 x 2
    const int gid = lane >> 2, tig = lane & 3;

    const int bz = blockIdx.z;
    const int my = blockIdx.y;
    const int sp = KS ? (my >> 1) : 0;
    const int m0 = (KS ? (my & 1) : my) * 128;
    const int n0 = blockIdx.x * 64;

    const void* A = (const void*)((const uint32_t*)Av + strA * bz + (size_t)(KS ? sp * K : 0));
    const void* B;
    if (BF == 3)
        B = (const void*)((const __half*)Bv + strB * bz + (size_t)(KS ? sp * K : 0));
    else
        B = (const void*)((const uint32_t*)Bv + strB * bz + (size_t)(KS ? sp * K : 0));

    const uint32_t sb = smem_u32(smw);
    const int lrow = lane & 15, lhalf = (lane >> 4) & 1;
    const uint32_t aoff = (uint32_t)((warp_m * 32 + lrow) * TS) * 4 + lhalf * 16;
    const uint32_t boff = (uint32_t)((warp_n * 32 + lrow) * TS) * 4 + lhalf * 16;

    float acc[2][4][4];
    #pragma unroll
    for (int i = 0; i < 2; i++)
        #pragma unroll
        for (int j = 0; j < 4; j++)
            #pragma unroll
            for (int t = 0; t < 4; t++) acc[i][j][t] = 0.f;

    // stage chunk 0
    #pragma unroll
    for (int u = 0; u < 4; u++) {
        uint4 ra = op_ldg<AF, 128>(A, lda, m0, 0, tid + u * 256);
        op_sts<AF, 128>(ra, smw, smw + TAW, tid + u * 256);
    }
    #pragma unroll
    for (int u = 0; u < 2; u++) {
        uint4 rb = op_ldg<BF, 64>(B, ldb, n0, 0, tid + u * 256);
        op_sts<BF, 64>(rb, smw + 2 * TAW, smw + 2 * TAW + TBW, tid + u * 256);
    }
    __syncthreads();

    const int nc = K >> 5;
    for (int c = 0; c < nc; c++) {
        const int cur = c & 1;
        uint4 pa[4], pb[2];
        const bool pf = (c + 1) < nc;
        if (pf) {
            const int k0 = (c + 1) << 5;
            #pragma unroll
            for (int u = 0; u < 4; u++) pa[u] = op_ldg<AF, 128>(A, lda, m0, k0, tid + u * 256);
            #pragma unroll
            for (int u = 0; u < 2; u++) pb[u] = op_ldg<BF, 64>(B, ldb, n0, k0, tid + u * 256);
        }

        const uint32_t base = sb + (uint32_t)cur * (BUFW * 4);
        #pragma unroll
        for (int s = 0; s < 2; s++) {
            uint32_t ah[2][4], al[2][4];
            #pragma unroll
            for (int mt = 0; mt < 2; mt++) {
                ldsm4(ah[mt], base + aoff + mt * (16 * TS * 4) + s * 32);
                ldsm4(al[mt], base + TAW * 4 + aoff + mt * (16 * TS * 4) + s * 32);
            }
            uint32_t bh[2][4], bl[2][4];
            #pragma unroll
            for (int np = 0; np < 2; np++) {
                ldsm4(bh[np], base + 2 * TAW * 4 + boff + np * (16 * TS * 4) + s * 32);
                if (SPLITB)
                    ldsm4(bl[np], base + (2 * TAW + TBW) * 4 + boff + np * (16 * TS * 4) + s * 32);
            }
            #pragma unroll
            for (int np = 0; np < 2; np++)
                #pragma unroll
                for (int h = 0; h < 2; h++) {
                    const int nt = np * 2 + h;
                    const uint32_t B0h = bh[np][h], B1h = bh[np][2 + h];
                    #pragma unroll
                    for (int mt = 0; mt < 2; mt++) {
                        mma_fp16(acc[mt][nt], ah[mt], B0h, B1h);
                        if (SPLITB)
                            mma_fp16(acc[mt][nt], ah[mt], bl[np][h], bl[np][2 + h]);
                        mma_fp16(acc[mt][nt], al[mt], B0h, B1h);
                    }
                }
        }

        if (pf) {
            uint32_t* nb = smw + (cur ^ 1) * BUFW;
            #pragma unroll
            for (int u = 0; u < 4; u++) op_sts<AF, 128>(pa[u], nb, nb + TAW, tid + u * 256);
            #pragma unroll
            for (int u = 0; u < 2; u++) op_sts<BF, 64>(pb[u], nb + 2 * TAW, nb + 2 * TAW + TBW, tid + u * 256);
        }
        __syncthreads();
    }

    if (EPI == 0) {
        float* C = ((KS && sp) ? C2 : (float*)Cv) + strC * bz;
        const float* Res = (!KS && res) ? res + strC * bz : nullptr;
        #pragma unroll
        for (int mt = 0; mt < 2; mt++) {
            const int r0i = m0 + warp_m * 32 + mt * 16 + gid;
            const int r1i = r0i + 8;
            const float b0f = bias ? bias[r0i] : 0.f;
            const float b1f = bias ? bias[r1i] : 0.f;
            #pragma unroll
            for (int nt = 0; nt < 4; nt++) {
                const int cc = n0 + warp_n * 32 + nt * 8 + 2 * tig;
                float v0 = acc[mt][nt][0] * alpha + b0f;
                float v1 = acc[mt][nt][1] * alpha + b0f;
                float v2 = acc[mt][nt][2] * alpha + b1f;
                float v3 = acc[mt][nt][3] * alpha + b1f;
                const size_t o0 = (size_t)r0i * ldc + cc;
                const size_t o1 = (size_t)r1i * ldc + cc;
                if (Res) {
                    float2 ra = *(const float2*)(Res + o0);
                    float2 rb = *(const float2*)(Res + o1);
                    v0 += ra.x; v1 += ra.y; v2 += rb.x; v3 += rb.y;
                }
                *(float2*)(C + o0) = make_float2(v0, v1);
                *(float2*)(C + o1) = make_float2(v2, v3);
            }
        }
    } else if (EPI == 1) {
        // packed transposed store: out[n0+nl][m0+rl]
        uint32_t* stg = smw;   // 128 x 65
        #pragma unroll
        for (int mt = 0; mt < 2; mt++) {
            const int ra = warp_m * 32 + mt * 16 + gid;
            const float b0f = bias ? bias[m0 + ra] : 0.f;
            const float b1f = bias ? bias[m0 + ra + 8] : 0.f;
            #pragma unroll
            for (int nt = 0; nt < 4; nt++) {
                const int cl = warp_n * 32 + nt * 8 + 2 * tig;
                stg[ra * 65 + cl]           = pack_pk(acc[mt][nt][0] * alpha + b0f);
                stg[ra * 65 + cl + 1]       = pack_pk(acc[mt][nt][1] * alpha + b0f);
                stg[(ra + 8) * 65 + cl]     = pack_pk(acc[mt][nt][2] * alpha + b1f);
                stg[(ra + 8) * 65 + cl + 1] = pack_pk(acc[mt][nt][3] * alpha + b1f);
            }
        }
        __syncthreads();
        uint32_t* out = (uint32_t*)Cv + strC * bz;
        const int rl = tid & 127, nlb = tid >> 7;
        #pragma unroll 8
        for (int i = 0; i < 32; i++) {
            const int nl = nlb + 2 * i;
            out[(size_t)(n0 + nl) * ldc + m0 + rl] = stg[rl * 65 + nl];
        }
    } else {
        // packed direct store: out[m][n]
        uint32_t* out = (uint32_t*)Cv + strC * bz;
        #pragma unroll
        for (int mt = 0; mt < 2; mt++) {
            const int r0i = m0 + warp_m * 32 + mt * 16 + gid;
            const int r1i = r0i + 8;
            const float b0f = bias ? bias[r0i] : 0.f;
            const float b1f = bias ? bias[r1i] : 0.f;
            #pragma unroll
            for (int nt = 0; nt < 4; nt++) {
                const int cc = n0 + warp_n * 32 + nt * 8 + 2 * tig;
                uint2 w0 = make_uint2(pack_pk(acc[mt][nt][0] * alpha + b0f),
                                      pack_pk(acc[mt][nt][1] * alpha + b0f));
                uint2 w1 = make_uint2(pack_pk(acc[mt][nt][2] * alpha + b1f),
                                      pack_pk(acc[mt][nt][3] * alpha + b1f));
                *(uint2*)(out + (size_t)r0i * ldc + cc) = w0;
                *(uint2*)(out + (size_t)r1i * ldc + cc) = w1;
            }
        }
    }
}

// ---------------- GroupNorm -> packed fp16 hn^T [b][n][c] ----------------
__global__ void __launch_bounds__(256) groupnorm_kernel(
    const float* __restrict__ x, const float* __restrict__ gamma,
    const float* __restrict__ beta, uint32_t* __restrict__ hnT)
{
    const int bg = blockIdx.x;
    const int b = bg / G_GROUPS, g = bg % G_GROUPS;
    const int c0 = g * CPG;
    const float* xp = x + ((size_t)b * C_DIM + c0) * N_POS;
    const int tid = threadIdx.x;
    const int NEL = CPG * N_POS;

    float s = 0.f, s2 = 0.f;
    for (int i = tid; i < NEL; i += 256) {
        float v = xp[i];
        s += v; s2 += v * v;
    }
    __shared__ float sh0[256], sh1[256];
    sh0[tid] = s; sh1[tid] = s2;
    __syncthreads();
    for (int o = 128; o > 0; o >>= 1) {
        if (tid < o) { sh0[tid] += sh0[tid + o]; sh1[tid] += sh1[tid + o]; }
        __syncthreads();
    }
    const float mean = sh0[0] * (1.0f / NEL);
    const float var  = sh1[0] * (1.0f / NEL) - mean * mean;
    const float rstd = rsqrtf(var + EPS);

    float gam[CPG], bet[CPG];
    #pragma unroll
    for (int j = 0; j < CPG; j++) {
        gam[j] = gamma[c0 + j] * rstd;
        bet[j] = beta[c0 + j] - mean * gam[j];
    }
    uint32_t* hp = hnT + (size_t)b * N_POS * C_DIM + c0;
    for (int n = tid; n < N_POS; n += 256) {
        uint32_t w[8];
        #pragma unroll
        for (int j = 0; j < 8; j++)
            w[j] = pack_pk(xp[(size_t)j * N_POS + n] * gam[j] + bet[j]);
        uint32_t* d = hp + (size_t)n * C_DIM;
        *(uint4*)d       = make_uint4(w[0], w[1], w[2], w[3]);
        *(uint4*)(d + 4) = make_uint4(w[4], w[5], w[6], w[7]);
    }
}

// ---------------- row stats: max + 1/sum(exp) per logit row ----------------
__global__ void __launch_bounds__(256) stats_kernel(
    const float* __restrict__ attn, float* __restrict__ rmax, float* __restrict__ rinv)
{
    const size_t row = blockIdx.x;
    const float* p = attn + row * N_POS;
    const int tid = threadIdx.x;
    float v[16];
    float mx = -1e30f;
    #pragma unroll
    for (int i = 0; i < 16; i++) {
        v[i] = p[tid + i * 256];
        mx = fmaxf(mx, v[i]);
    }
    __shared__ float sh[256];
    sh[tid] = mx;
    __syncthreads();
    for (int o = 128; o > 0; o >>= 1) {
        if (tid < o) sh[tid] = fmaxf(sh[tid], sh[tid + o]);
        __syncthreads();
    }
    mx = sh[0];
    __syncthreads();
    float s = 0.f;
    #pragma unroll
    for (int i = 0; i < 16; i++) s += __expf(v[i] - mx);
    sh[tid] = s;
    __syncthreads();
    for (int o = 128; o > 0; o >>= 1) {
        if (tid < o) sh[tid] += sh[tid + o];
        __syncthreads();
    }
    if (tid == 0) {
        rmax[row] = mx;
        rinv[row] = 1.0f / sh[0];
    }
}

// ---------------- normalize once: out2[b][m][n] (fp32, transposed) + p16[b][n][m] (fp16) ----------------
__global__ void __launch_bounds__(256) transposeP_kernel(
    const float* __restrict__ attn, const float* __restrict__ rmax,
    const float* __restrict__ rinv, float* __restrict__ out2, __half* __restrict__ p16)
{
    __shared__ float tile[32][33];
    const int bz = blockIdx.z;
    const int m0 = blockIdx.x * 32;
    const int n0 = blockIdx.y * 32;
    const float* src = attn + (size_t)bz * N_POS * N_POS;
    float*       dst = out2 + (size_t)bz * N_POS * N_POS;
    __half*      pd  = p16  + (size_t)bz * N_POS * N_POS;
    const int tx = threadIdx.x, ty = threadIdx.y;
    #pragma unroll
    for (int j = 0; j < 4; j++) {
        const int n = n0 + ty + j * 8;
        const float mx = rmax[bz * N_POS + n];
        const float iv = rinv[bz * N_POS + n];
        const float pv = __expf(src[(size_t)n * N_POS + m0 + tx] - mx) * iv;
        tile[ty + j * 8][tx] = pv;
        pd[(size_t)n * N_POS + m0 + tx] = __float2half(pv);
    }
    __syncthreads();
    #pragma unroll
    for (int j = 0; j < 4; j++)
        dst[(size_t)(m0 + ty + j * 8) * N_POS + n0 + tx] = tile[tx][ty + j * 8];
}

// ---------------- partial reduce: hv = pt0 + pt1 ----------------
__global__ void __launch_bounds__(256) reduce_kernel(
    const float* __restrict__ a, const float* __restrict__ b, float* __restrict__ o, int n4)
{
    int i = blockIdx.x * 256 + threadIdx.x;
    if (i < n4) {
        float4 va = ((const float4*)a)[i];
        float4 vb = ((const float4*)b)[i];
        ((float4*)o)[i] = make_float4(va.x + vb.x, va.y + vb.y, va.z + vb.z, va.w + vb.w);
    }
}

// ---------------- launch ----------------
#define SMEM_S1 ((2 * TAW + 2 * TBW) * 2 * 4)   // splitB buffers: 61440 B
#define SMEM_S0 ((2 * TAW + TBW) * 2 * 4)       // single-B buffers: 51200 B

extern "C" void kernel_launch(void* const* d_in, const int* in_sizes, int n_in,
                              void* d_out, int out_size)
{
    const float* x     = (const float*)d_in[0];
    const float* gamma = (const float*)d_in[1];
    const float* beta  = (const float*)d_in[2];
    const float* wq    = (const float*)d_in[3];
    const float* bq    = (const float*)d_in[4];
    const float* wk    = (const float*)d_in[5];
    const float* bk    = (const float*)d_in[6];
    const float* wv    = (const float*)d_in[7];
    const float* bv    = (const float*)d_in[8];
    const float* wp    = (const float*)d_in[9];
    const float* bp    = (const float*)d_in[10];

    float* out1 = (float*)d_out;
    float* out2 = out1 + (size_t)B_DIM * C_DIM * N_POS;

    uint32_t *hnT, *qT, *kT, *v16;
    float *attn, *pt0, *pt1, *hv, *rmax, *rinv;
    __half* p16;
    cudaGetSymbolAddress((void**)&hnT, g_hnT);
    cudaGetSymbolAddress((void**)&qT,  g_qT);
    cudaGetSymbolAddress((void**)&kT,  g_kT);
    cudaGetSymbolAddress((void**)&v16, g_v16);
    cudaGetSymbolAddress((void**)&attn, g_attn);
    cudaGetSymbolAddress((void**)&p16, g_p16);
    cudaGetSymbolAddress((void**)&pt0, g_pt0);
    cudaGetSymbolAddress((void**)&pt1, g_pt1);
    cudaGetSymbolAddress((void**)&hv,  g_hv);
    cudaGetSymbolAddress((void**)&rmax, g_rmax);
    cudaGetSymbolAddress((void**)&rinv, g_rinv);

    auto GQK = gemm_tc<0, 2, 1, 1, 0>;   // proj q/k  -> packed [n][c]
    auto GV  = gemm_tc<0, 2, 1, 2, 0>;   // proj v    -> packed [c][m]
    auto GS  = gemm_tc<2, 2, 1, 0, 0>;   // QK logits -> fp32
    auto GAV = gemm_tc<2, 3, 0, 0, 1>;   // AV (P fp16 single), K-split 2
    auto GP  = gemm_tc<0, 1, 1, 0, 0>;   // final proj (+bias +residual)
    cudaFuncSetAttribute(GQK, cudaFuncAttributeMaxDynamicSharedMemorySize, SMEM_S1);
    cudaFuncSetAttribute(GV,  cudaFuncAttributeMaxDynamicSharedMemorySize, SMEM_S1);
    cudaFuncSetAttribute(GS,  cudaFuncAttributeMaxDynamicSharedMemorySize, SMEM_S1);
    cudaFuncSetAttribute(GAV, cudaFuncAttributeMaxDynamicSharedMemorySize, SMEM_S0);
    cudaFuncSetAttribute(GP,  cudaFuncAttributeMaxDynamicSharedMemorySize, SMEM_S1);

    const size_t NC  = (size_t)N_POS * C_DIM;    // 1048576 (words / elems)
    const size_t CN  = (size_t)C_DIM * N_POS;
    const size_t NN2 = (size_t)N_POS * N_POS;
    const float scale = 0.0625f;                 // 256^-0.5

    // 1) GroupNorm -> packed hn^T
    groupnorm_kernel<<<B_DIM * G_GROUPS, 256>>>(x, gamma, beta, hnT);

    // 2) projections (M=256 x N=4096 x K=256)
    dim3 gp(N_POS / 64, 2, B_DIM);               // (64, 2, 2)
    GQK<<<gp, 256, SMEM_S1>>>(wq, hnT, qT, C_DIM, C_DIM, C_DIM, C_DIM,
                              bq, nullptr, 1.f, 0, NC, NC, nullptr);
    GQK<<<gp, 256, SMEM_S1>>>(wk, hnT, kT, C_DIM, C_DIM, C_DIM, C_DIM,
                              bk, nullptr, 1.f, 0, NC, NC, nullptr);
    GV <<<gp, 256, SMEM_S1>>>(wv, hnT, v16, C_DIM, C_DIM, C_DIM, N_POS,
                              bv, nullptr, 1.f, 0, NC, CN, nullptr);

    // 3) raw logits s[n][m] = scale * q.k  (A=qT pk, B=kT pk)
    dim3 gqk(N_POS / 64, N_POS / 128, B_DIM);    // (64, 32, 2)
    GS<<<gqk, 256, SMEM_S1>>>(qT, kT, attn, C_DIM, C_DIM, C_DIM, N_POS,
                              nullptr, nullptr, scale, NC, NC, NN2, nullptr);

    // 4) row stats
    stats_kernel<<<B_DIM * N_POS, 256>>>(attn, rmax, rinv);

    // 5) one normalize pass: out2 (fp32 P^T, final output) + p16 (fp16 P)
    transposeP_kernel<<<dim3(N_POS / 32, N_POS / 32, B_DIM), dim3(32, 8)>>>(
        attn, rmax, rinv, out2, p16);

    // 6) AV partials: hv[c][n] = sum_m v[c][m] P[n][m], K split in 2 (grid.y=4)
    dim3 gav(N_POS / 64, 4, B_DIM);              // (64, 4, 2) = 512 CTAs
    GAV<<<gav, 256, SMEM_S0>>>(v16, p16, pt0, N_POS / 2, N_POS, N_POS, N_POS,
                               nullptr, nullptr, 1.f, CN, NN2, CN, pt1);

    // 7) hv = pt0 + pt1
    reduce_kernel<<<(int)((B_DIM * CN / 4 + 255) / 256), 256>>>(pt0, pt1, hv,
                                                                (int)(B_DIM * CN / 4));

    // 8) out1 = x + wp*hv + bp
    GP<<<gp, 256, SMEM_S1>>>(wp, hv, out1, C_DIM, C_DIM, N_POS, N_POS,
                             bp, x, 1.f, 0, CN, CN, nullptr);
}

// round 9
// speedup vs baseline: 2.6509x; 1.0300x over previous
#include <cuda_runtime.h>
#include <cuda_fp16.h>
#include <math.h>
#include <stdint.h>

#define B_DIM 2
#define C_DIM 256
#define N_POS 4096
#define G_GROUPS 32
#define CPG 8
#define EPS 1e-6f
#define NCHUNK 64   // QK m-chunks (N_POS/64)

// ---------------- scratch (device globals; no allocation allowed) ----------------
__device__ __align__(16) uint32_t g_hnT[(size_t)B_DIM * N_POS * C_DIM];  // pk(hi|lo) [b][n][c]
__device__ __align__(16) uint32_t g_qT [(size_t)B_DIM * N_POS * C_DIM];  // pk [b][n][c]
__device__ __align__(16) uint32_t g_kT [(size_t)B_DIM * N_POS * C_DIM];  // pk [b][m][c]
__device__ __align__(16) uint32_t g_v16[(size_t)B_DIM * C_DIM * N_POS];  // pk [b][c][m]
__device__ __align__(16) uint32_t g_hvT[(size_t)B_DIM * N_POS * C_DIM];  // pk [b][n][c]
__device__ __align__(16) float    g_attn[(size_t)B_DIM * N_POS * N_POS]; // raw logits
__device__ __align__(16) __half   g_p16[(size_t)B_DIM * N_POS * N_POS];  // softmax fp16 [b][n][m]
__device__ __align__(16) float    g_wcat[768 * 256];
__device__ float g_bcat[768];
__device__ float g_pmax[(size_t)B_DIM * NCHUNK * N_POS];
__device__ float g_psum[(size_t)B_DIM * NCHUNK * N_POS];
__device__ float g_rmax[(size_t)B_DIM * N_POS];
__device__ float g_rinv[(size_t)B_DIM * N_POS];

// =================== smem tile geometry ===================
// A tile 128 rows x 32 k fp16 (16 words/row), B tile 64 x 32. Row stride TS=20
// words (odd /4 -> conflict-free ldmatrix phases).
#define TS 20
#define TAW (128 * TS)
#define TBW (64 * TS)

// =================== PTX helpers ===================
__device__ __forceinline__ uint32_t smem_u32(const void* p) {
    uint32_t a;
    asm("{ .reg .u64 t; cvta.to.shared.u64 t, %1; cvt.u32.u64 %0, t; }"
        : "=r"(a) : "l"(p));
    return a;
}
__device__ __forceinline__ void ldsm4(uint32_t* r, uint32_t addr) {
    asm volatile("ldmatrix.sync.aligned.m8n8.x4.shared.b16 {%0,%1,%2,%3}, [%4];"
                 : "=r"(r[0]), "=r"(r[1]), "=r"(r[2]), "=r"(r[3]) : "r"(addr));
}
__device__ __forceinline__ void mma_fp16(float* c, const uint32_t* a,
                                         uint32_t b0, uint32_t b1) {
    asm volatile(
        "mma.sync.aligned.m16n8k16.row.col.f32.f16.f16.f32 "
        "{%0,%1,%2,%3}, {%4,%5,%6,%7}, {%8,%9}, {%0,%1,%2,%3};"
        : "+f"(c[0]), "+f"(c[1]), "+f"(c[2]), "+f"(c[3])
        : "r"(a[0]), "r"(a[1]), "r"(a[2]), "r"(a[3]), "r"(b0), "r"(b1));
}

// packed fp16 split word: low16 = hi, high16 = lo
__device__ __forceinline__ uint32_t pack_pk(float x) {
    __half h = __float2half_rn(x);
    __half l = __float2half_rn(x - __half2float(h));
    return (uint32_t)__half_as_ushort(h) | ((uint32_t)__half_as_ushort(l) << 16);
}
__device__ __forceinline__ void split2(float x0, float x1, uint32_t& h, uint32_t& l) {
    __half h0 = __float2half_rn(x0), h1 = __float2half_rn(x1);
    __half l0 = __float2half_rn(x0 - __half2float(h0));
    __half l1 = __float2half_rn(x1 - __half2float(h1));
    h = (uint32_t)__half_as_ushort(h0) | ((uint32_t)__half_as_ushort(h1) << 16);
    l = (uint32_t)__half_as_ushort(l0) | ((uint32_t)__half_as_ushort(l1) << 16);
}

// =================== operand staging ===================
// formats: 0 = fp32 row-major [r][k], 2 = packed-fp16 [r][k], 3 = plain fp16 [r][k]
template<int F>
__device__ __forceinline__ uint4 op_ldg(const void* src, int ld, int r0, int k0, int qi) {
    const int kq = qi & 7, r = qi >> 3;
    uint4 out;
    if (F == 0) {
        float4 v = *(const float4*)((const float*)src + (size_t)(r0 + r) * ld + k0 + 4 * kq);
        out = *(uint4*)&v;
    } else if (F == 2) {
        out = *(const uint4*)((const uint32_t*)src + (size_t)(r0 + r) * ld + k0 + 4 * kq);
    } else {
        uint2 v = *(const uint2*)((const __half*)src + (size_t)(r0 + r) * ld + k0 + 4 * kq);
        out = make_uint4(v.x, v.y, 0u, 0u);
    }
    return out;
}
template<int F>
__device__ __forceinline__ void op_sts(uint4 raw, uint32_t* __restrict__ hi,
                                       uint32_t* __restrict__ lo, int qi) {
    const int kq = qi & 7, r = qi >> 3;
    const int w = r * TS + 2 * kq;
    if (F == 0) {
        const float* x = (const float*)&raw;
        uint32_t h0, l0, h1, l1;
        split2(x[0], x[1], h0, l0);
        split2(x[2], x[3], h1, l1);
        *(uint2*)(hi + w) = make_uint2(h0, h1);
        *(uint2*)(lo + w) = make_uint2(l0, l1);
    } else if (F == 2) {
        *(uint2*)(hi + w) = make_uint2(__byte_perm(raw.x, raw.y, 0x5410),
                                       __byte_perm(raw.z, raw.w, 0x5410));
        *(uint2*)(lo + w) = make_uint2(__byte_perm(raw.x, raw.y, 0x7632),
                                       __byte_perm(raw.z, raw.w, 0x7632));
    } else {
        *(uint2*)(hi + w) = make_uint2(raw.x, raw.y);
    }
}

// =================== fp16-split HMMA GEMM ===================
// C[m,n] = alpha * sum_k A[m,k]*B[n,k]. CTA 128(M) x 64(N), K-chunk 32,
// 256 threads (8 warps: 4m x 2n of 32x32 warp tiles), double-buffered smem.
// SPLITA/SPLITB derived from formats (F3 = single fp16).
// EPI: 0 fp32 (+bias +res) | 2 packed direct [m][n] | 3 fp32 + partial softmax
//      stats | 4 fused QKV epilogue (q/k transposed-packed, v direct-packed).
template<int AF, int BF, int EPI>
__global__ void __launch_bounds__(256, 2) gemm_tc(
    const void* __restrict__ Av, const void* __restrict__ Bv,
    void* __restrict__ Cv, void* __restrict__ Cv2, void* __restrict__ Cv3,
    int K, int lda, int ldb, int ldc,
    const float* __restrict__ bias, const float* __restrict__ res,
    float alpha, size_t sAb, size_t sBb, size_t sCb)
{
    constexpr int SPLITA = (AF != 3);
    constexpr int SPLITB = (BF != 3);
    constexpr int OFF_BH = TAW * (SPLITA ? 2 : 1);
    constexpr int BUFW = OFF_BH + TBW * (SPLITB ? 2 : 1);
    extern __shared__ __align__(16) uint32_t smw[];

    const int tid = threadIdx.x;
    const int lane = tid & 31, wid = tid >> 5;
    const int warp_m = wid & 3, warp_n = wid >> 2;
    const int gid = lane >> 2, tig = lane & 3;
    const int bz = blockIdx.z;
    const int my = blockIdx.y;
    const int m0 = my * 128;
    const int n0 = blockIdx.x * 64;

    const char* A = (const char*)Av + sAb * bz;
    const char* B = (const char*)Bv + sBb * bz;

    const uint32_t sb = smem_u32(smw);
    const int lrow = lane & 15, lhalf = (lane >> 4) & 1;
    const uint32_t aoff = (uint32_t)((warp_m * 32 + lrow) * TS) * 4 + lhalf * 16;
    const uint32_t boff = (uint32_t)((warp_n * 32 + lrow) * TS) * 4 + lhalf * 16;

    float acc[2][4][4];
    #pragma unroll
    for (int i = 0; i < 2; i++)
        #pragma unroll
        for (int j = 0; j < 4; j++)
            #pragma unroll
            for (int t = 0; t < 4; t++) acc[i][j][t] = 0.f;

    // stage chunk 0
    #pragma unroll
    for (int u = 0; u < 4; u++) {
        uint4 ra = op_ldg<AF>(A, lda, m0, 0, tid + u * 256);
        op_sts<AF>(ra, smw, smw + (SPLITA ? TAW : 0), tid + u * 256);
    }
    #pragma unroll
    for (int u = 0; u < 2; u++) {
        uint4 rb = op_ldg<BF>(B, ldb, n0, 0, tid + u * 256);
        op_sts<BF>(rb, smw + OFF_BH, smw + OFF_BH + (SPLITB ? TBW : 0), tid + u * 256);
    }
    __syncthreads();

    const int nc = K >> 5;
    for (int c = 0; c < nc; c++) {
        const int cur = c & 1;
        uint4 pa[4], pb[2];
        const bool pf = (c + 1) < nc;
        if (pf) {
            const int k0 = (c + 1) << 5;
            #pragma unroll
            for (int u = 0; u < 4; u++) pa[u] = op_ldg<AF>(A, lda, m0, k0, tid + u * 256);
            #pragma unroll
            for (int u = 0; u < 2; u++) pb[u] = op_ldg<BF>(B, ldb, n0, k0, tid + u * 256);
        }

        const uint32_t base = sb + (uint32_t)cur * (BUFW * 4);
        #pragma unroll
        for (int s = 0; s < 2; s++) {
            uint32_t ah[2][4], al[2][4], bh[2][4], bl[2][4];
            #pragma unroll
            for (int mt = 0; mt < 2; mt++) {
                ldsm4(ah[mt], base + aoff + mt * (16 * TS * 4) + s * 32);
                if (SPLITA)
                    ldsm4(al[mt], base + TAW * 4 + aoff + mt * (16 * TS * 4) + s * 32);
            }
            #pragma unroll
            for (int np = 0; np < 2; np++) {
                ldsm4(bh[np], base + OFF_BH * 4 + boff + np * (16 * TS * 4) + s * 32);
                if (SPLITB)
                    ldsm4(bl[np], base + (OFF_BH + TBW) * 4 + boff + np * (16 * TS * 4) + s * 32);
            }
            #pragma unroll
            for (int np = 0; np < 2; np++)
                #pragma unroll
                for (int h = 0; h < 2; h++) {
                    const int nt = np * 2 + h;
                    const uint32_t B0h = bh[np][h], B1h = bh[np][2 + h];
                    #pragma unroll
                    for (int mt = 0; mt < 2; mt++) {
                        mma_fp16(acc[mt][nt], ah[mt], B0h, B1h);
                        if (SPLITB)
                            mma_fp16(acc[mt][nt], ah[mt], bl[np][h], bl[np][2 + h]);
                        if (SPLITA)
                            mma_fp16(acc[mt][nt], al[mt], B0h, B1h);
                    }
                }
        }

        if (pf) {
            uint32_t* nb = smw + (cur ^ 1) * BUFW;
            #pragma unroll
            for (int u = 0; u < 4; u++)
                op_sts<AF>(pa[u], nb, nb + (SPLITA ? TAW : 0), tid + u * 256);
            #pragma unroll
            for (int u = 0; u < 2; u++)
                op_sts<BF>(pb[u], nb + OFF_BH, nb + OFF_BH + (SPLITB ? TBW : 0), tid + u * 256);
        }
        __syncthreads();
    }

    if (EPI == 0) {
        float* C = (float*)((char*)Cv + sCb * bz);
        const float* Res = res ? (const float*)((const char*)res + sCb * bz) : nullptr;
        #pragma unroll
        for (int mt = 0; mt < 2; mt++) {
            const int r0i = m0 + warp_m * 32 + mt * 16 + gid;
            const int r1i = r0i + 8;
            const float b0f = bias ? bias[r0i] : 0.f;
            const float b1f = bias ? bias[r1i] : 0.f;
            #pragma unroll
            for (int nt = 0; nt < 4; nt++) {
                const int cc = n0 + warp_n * 32 + nt * 8 + 2 * tig;
                float v0 = acc[mt][nt][0] * alpha + b0f;
                float v1 = acc[mt][nt][1] * alpha + b0f;
                float v2 = acc[mt][nt][2] * alpha + b1f;
                float v3 = acc[mt][nt][3] * alpha + b1f;
                const size_t o0 = (size_t)r0i * ldc + cc;
                const size_t o1 = (size_t)r1i * ldc + cc;
                if (Res) {
                    float2 ra = *(const float2*)(Res + o0);
                    float2 rb = *(const float2*)(Res + o1);
                    v0 += ra.x; v1 += ra.y; v2 += rb.x; v3 += rb.y;
                }
                *(float2*)(C + o0) = make_float2(v0, v1);
                *(float2*)(C + o1) = make_float2(v2, v3);
            }
        }
    } else if (EPI == 2) {
        // packed direct store (no bias): out[m][n]
        uint32_t* out = (uint32_t*)((char*)Cv + sCb * bz);
        #pragma unroll
        for (int mt = 0; mt < 2; mt++) {
            const int r0i = m0 + warp_m * 32 + mt * 16 + gid;
            #pragma unroll
            for (int nt = 0; nt < 4; nt++) {
                const int cc = n0 + warp_n * 32 + nt * 8 + 2 * tig;
                *(uint2*)(out + (size_t)r0i * ldc + cc) =
                    make_uint2(pack_pk(acc[mt][nt][0]), pack_pk(acc[mt][nt][1]));
                *(uint2*)(out + (size_t)(r0i + 8) * ldc + cc) =
                    make_uint2(pack_pk(acc[mt][nt][2]), pack_pk(acc[mt][nt][3]));
            }
        }
    } else if (EPI == 3) {
        // fp32 logits + per-CTA partial softmax stats over this 64-col chunk
        float* C = (float*)((char*)Cv + sCb * bz);
        #pragma unroll
        for (int mt = 0; mt < 2; mt++)
            #pragma unroll
            for (int nt = 0; nt < 4; nt++)
                #pragma unroll
                for (int t = 0; t < 4; t++) acc[mt][nt][t] *= alpha;
        #pragma unroll
        for (int mt = 0; mt < 2; mt++) {
            const int r0i = m0 + warp_m * 32 + mt * 16 + gid;
            #pragma unroll
            for (int nt = 0; nt < 4; nt++) {
                const int cc = n0 + warp_n * 32 + nt * 8 + 2 * tig;
                *(float2*)(C + (size_t)r0i * ldc + cc) =
                    make_float2(acc[mt][nt][0], acc[mt][nt][1]);
                *(float2*)(C + (size_t)(r0i + 8) * ldc + cc) =
                    make_float2(acc[mt][nt][2], acc[mt][nt][3]);
            }
        }
        float* smax = (float*)smw;        // [128][2]
        float* ssum = smax + 256;         // [128][2]
        float rmx[2][2];
        #pragma unroll
        for (int mt = 0; mt < 2; mt++)
            #pragma unroll
            for (int hf = 0; hf < 2; hf++) {
                float m8 = -1e30f;
                #pragma unroll
                for (int nt = 0; nt < 4; nt++)
                    m8 = fmaxf(m8, fmaxf(acc[mt][nt][hf * 2], acc[mt][nt][hf * 2 + 1]));
                m8 = fmaxf(m8, __shfl_xor_sync(0xffffffffu, m8, 1));
                m8 = fmaxf(m8, __shfl_xor_sync(0xffffffffu, m8, 2));
                const int rl = warp_m * 32 + mt * 16 + hf * 8 + gid;
                if (tig == 0) smax[rl * 2 + warp_n] = m8;
            }
        __syncthreads();
        #pragma unroll
        for (int mt = 0; mt < 2; mt++)
            #pragma unroll
            for (int hf = 0; hf < 2; hf++) {
                const int rl = warp_m * 32 + mt * 16 + hf * 8 + gid;
                const float rm = fmaxf(smax[rl * 2], smax[rl * 2 + 1]);
                rmx[mt][hf] = rm;
                float s = 0.f;
                #pragma unroll
                for (int nt = 0; nt < 4; nt++)
                    s += __expf(acc[mt][nt][hf * 2] - rm) + __expf(acc[mt][nt][hf * 2 + 1] - rm);
                s += __shfl_xor_sync(0xffffffffu, s, 1);
                s += __shfl_xor_sync(0xffffffffu, s, 2);
                if (tig == 0) ssum[rl * 2 + warp_n] = s;
            }
        __syncthreads();
        if (tig == 0 && warp_n == 0) {
            float* pmax = (float*)Cv2;
            float* psum = (float*)Cv3;
            const size_t pb = ((size_t)bz * NCHUNK + blockIdx.x) * N_POS;
            #pragma unroll
            for (int mt = 0; mt < 2; mt++)
                #pragma unroll
                for (int hf = 0; hf < 2; hf++) {
                    const int rl = warp_m * 32 + mt * 16 + hf * 8 + gid;
                    pmax[pb + m0 + rl] = rmx[mt][hf];
                    psum[pb + m0 + rl] = ssum[rl * 2] + ssum[rl * 2 + 1];
                }
        }
    } else {
        // EPI 4: fused QKV epilogue. my 0-1 -> qT, 2-3 -> kT (transposed packed), 4-5 -> v16
        const int kind = my >> 1;
        if (kind < 2) {
            uint32_t* stg = smw;   // 128 x 65 staging
            #pragma unroll
            for (int mt = 0; mt < 2; mt++) {
                const int ra = warp_m * 32 + mt * 16 + gid;
                const float b0f = bias[m0 + ra];
                const float b1f = bias[m0 + ra + 8];
                #pragma unroll
                for (int nt = 0; nt < 4; nt++) {
                    const int cl = warp_n * 32 + nt * 8 + 2 * tig;
                    stg[ra * 65 + cl]           = pack_pk(acc[mt][nt][0] + b0f);
                    stg[ra * 65 + cl + 1]       = pack_pk(acc[mt][nt][1] + b0f);
                    stg[(ra + 8) * 65 + cl]     = pack_pk(acc[mt][nt][2] + b1f);
                    stg[(ra + 8) * 65 + cl + 1] = pack_pk(acc[mt][nt][3] + b1f);
                }
            }
            __syncthreads();
            uint32_t* out = (uint32_t*)((char*)(kind == 0 ? Cv : Cv2)
                            + (size_t)bz * ((size_t)N_POS * C_DIM * 4));
            const int c0l = (my & 1) * 128;
            const int rl = tid & 127, nlb = tid >> 7;
            #pragma unroll 8
            for (int i = 0; i < 32; i++) {
                const int nl = nlb + 2 * i;
                out[(size_t)(n0 + nl) * C_DIM + c0l + rl] = stg[rl * 65 + nl];
            }
        } else {
            uint32_t* out = (uint32_t*)((char*)Cv3 + (size_t)bz * ((size_t)C_DIM * N_POS * 4));
            #pragma unroll
            for (int mt = 0; mt < 2; mt++) {
                const int ra = warp_m * 32 + mt * 16 + gid;
                const int r0i = (m0 - 512) + ra;
                const float b0f = bias[m0 + ra];
                const float b1f = bias[m0 + ra + 8];
                #pragma unroll
                for (int nt = 0; nt < 4; nt++) {
                    const int cc = n0 + warp_n * 32 + nt * 8 + 2 * tig;
                    *(uint2*)(out + (size_t)r0i * N_POS + cc) =
                        make_uint2(pack_pk(acc[mt][nt][0] + b0f), pack_pk(acc[mt][nt][1] + b0f));
                    *(uint2*)(out + (size_t)(r0i + 8) * N_POS + cc) =
                        make_uint2(pack_pk(acc[mt][nt][2] + b1f), pack_pk(acc[mt][nt][3] + b1f));
                }
            }
        }
    }
}

// ---------------- weight concat: wcat[768][256], bcat[768] ----------------
__global__ void __launch_bounds__(256) pack_w(
    const float* __restrict__ wq, const float* __restrict__ wk, const float* __restrict__ wv,
    const float* __restrict__ bq, const float* __restrict__ bk, const float* __restrict__ bv,
    float* __restrict__ wcat, float* __restrict__ bcat)
{
    const int r = blockIdx.x, c = threadIdx.x;
    const float* w = r < 256 ? wq + (size_t)r * 256
                   : (r < 512 ? wk + (size_t)(r - 256) * 256 : wv + (size_t)(r - 512) * 256);
    wcat[(size_t)r * 256 + c] = w[c];
    if (c == 0)
        bcat[r] = r < 256 ? bq[r] : (r < 512 ? bk[r - 256] : bv[r - 512]);
}

// ---------------- GroupNorm -> packed fp16 hn^T [b][n][c] ----------------
__global__ void __launch_bounds__(256) groupnorm_kernel(
    const float* __restrict__ x, const float* __restrict__ gamma,
    const float* __restrict__ beta, uint32_t* __restrict__ hnT)
{
    const int bg = blockIdx.x;
    const int b = bg / G_GROUPS, g = bg % G_GROUPS;
    const int c0 = g * CPG;
    const float* xp = x + ((size_t)b * C_DIM + c0) * N_POS;
    const int tid = threadIdx.x;
    const int NEL = CPG * N_POS;

    float s = 0.f, s2 = 0.f;
    for (int i = tid; i < NEL; i += 256) {
        float v = xp[i];
        s += v; s2 += v * v;
    }
    __shared__ float sh0[256], sh1[256];
    sh0[tid] = s; sh1[tid] = s2;
    __syncthreads();
    for (int o = 128; o > 0; o >>= 1) {
        if (tid < o) { sh0[tid] += sh0[tid + o]; sh1[tid] += sh1[tid + o]; }
        __syncthreads();
    }
    const float mean = sh0[0] * (1.0f / NEL);
    const float var  = sh1[0] * (1.0f / NEL) - mean * mean;
    const float rstd = rsqrtf(var + EPS);

    float gam[CPG], bet[CPG];
    #pragma unroll
    for (int j = 0; j < CPG; j++) {
        gam[j] = gamma[c0 + j] * rstd;
        bet[j] = beta[c0 + j] - mean * gam[j];
    }
    uint32_t* hp = hnT + (size_t)b * N_POS * C_DIM + c0;
    for (int n = tid; n < N_POS; n += 256) {
        uint32_t w[8];
        #pragma unroll
        for (int j = 0; j < 8; j++)
            w[j] = pack_pk(xp[(size_t)j * N_POS + n] * gam[j] + bet[j]);
        uint32_t* d = hp + (size_t)n * C_DIM;
        *(uint4*)d       = make_uint4(w[0], w[1], w[2], w[3]);
        *(uint4*)(d + 4) = make_uint4(w[4], w[5], w[6], w[7]);
    }
}

// ---------------- combine partial stats -> rmax, rinv ----------------
__global__ void __launch_bounds__(256) combine_kernel(
    const float* __restrict__ pmax, const float* __restrict__ psum,
    float* __restrict__ rmax, float* __restrict__ rinv)
{
    const int idx = blockIdx.x * 256 + threadIdx.x;   // b*4096 + n
    const int b = idx >> 12, n = idx & (N_POS - 1);
    const float* pm = pmax + ((size_t)b * NCHUNK << 12);
    const float* ps = psum + ((size_t)b * NCHUNK << 12);
    float gm = -1e30f;
    #pragma unroll 8
    for (int c = 0; c < NCHUNK; c++) gm = fmaxf(gm, pm[(c << 12) + n]);
    float s = 0.f;
    #pragma unroll 8
    for (int c = 0; c < NCHUNK; c++) s += ps[(c << 12) + n] * __expf(pm[(c << 12) + n] - gm);
    rmax[idx] = gm;
    rinv[idx] = 1.0f / s;
}

// ---------------- normalize once: out2[b][m][n] fp32 + p16[b][n][m] fp16 ----------------
__global__ void __launch_bounds__(256) transposeP_kernel(
    const float* __restrict__ attn, const float* __restrict__ rmax,
    const float* __restrict__ rinv, float* __restrict__ out2, __half* __restrict__ p16)
{
    __shared__ float tile[32][33];
    const int bz = blockIdx.z;
    const int m0 = blockIdx.x * 32;
    const int n0 = blockIdx.y * 32;
    const float* src = attn + (size_t)bz * N_POS * N_POS;
    float*       dst = out2 + (size_t)bz * N_POS * N_POS;
    __half*      pd  = p16  + (size_t)bz * N_POS * N_POS;
    const int tx = threadIdx.x, ty = threadIdx.y;
    #pragma unroll
    for (int j = 0; j < 4; j++) {
        const int n = n0 + ty + j * 8;
        const float mx = rmax[bz * N_POS + n];
        const float iv = rinv[bz * N_POS + n];
        const float pv = __expf(src[(size_t)n * N_POS + m0 + tx] - mx) * iv;
        tile[ty + j * 8][tx] = pv;
        pd[(size_t)n * N_POS + m0 + tx] = __float2half(pv);
    }
    __syncthreads();
    #pragma unroll
    for (int j = 0; j < 4; j++)
        dst[(size_t)(m0 + ty + j * 8) * N_POS + n0 + tx] = tile[tx][ty + j * 8];
}

// ---------------- launch ----------------
#define SMEM_FULL ((2 * TAW + 2 * TBW) * 2 * 4)   // split A + split B: 61440 B
#define SMEM_AV   ((TAW + 2 * TBW) * 2 * 4)       // single A + split B: 40960 B

extern "C" void kernel_launch(void* const* d_in, const int* in_sizes, int n_in,
                              void* d_out, int out_size)
{
    const float* x     = (const float*)d_in[0];
    const float* gamma = (const float*)d_in[1];
    const float* beta  = (const float*)d_in[2];
    const float* wq    = (const float*)d_in[3];
    const float* bq    = (const float*)d_in[4];
    const float* wk    = (const float*)d_in[5];
    const float* bk    = (const float*)d_in[6];
    const float* wv    = (const float*)d_in[7];
    const float* bv    = (const float*)d_in[8];
    const float* wp    = (const float*)d_in[9];
    const float* bp    = (const float*)d_in[10];

    float* out1 = (float*)d_out;
    float* out2 = out1 + (size_t)B_DIM * C_DIM * N_POS;

    uint32_t *hnT, *qT, *kT, *v16, *hvT;
    float *attn, *wcat, *bcat, *pmax, *psum, *rmax, *rinv;
    __half* p16;
    cudaGetSymbolAddress((void**)&hnT,  g_hnT);
    cudaGetSymbolAddress((void**)&qT,   g_qT);
    cudaGetSymbolAddress((void**)&kT,   g_kT);
    cudaGetSymbolAddress((void**)&v16,  g_v16);
    cudaGetSymbolAddress((void**)&hvT,  g_hvT);
    cudaGetSymbolAddress((void**)&attn, g_attn);
    cudaGetSymbolAddress((void**)&p16,  g_p16);
    cudaGetSymbolAddress((void**)&wcat, g_wcat);
    cudaGetSymbolAddress((void**)&bcat, g_bcat);
    cudaGetSymbolAddress((void**)&pmax, g_pmax);
    cudaGetSymbolAddress((void**)&psum, g_psum);
    cudaGetSymbolAddress((void**)&rmax, g_rmax);
    cudaGetSymbolAddress((void**)&rinv, g_rinv);

    auto GQKV = gemm_tc<0, 2, 4>;   // wcat x hnT -> qT/kT/v16 (fused epilogue)
    auto GS   = gemm_tc<2, 2, 3>;   // qT x kT -> logits + partial stats
    auto GAV  = gemm_tc<3, 2, 2>;   // p16 x v16 -> hvT packed
    auto GP   = gemm_tc<0, 2, 0>;   // wp x hvT -> out1 (+bias +residual)
    cudaFuncSetAttribute(GQKV, cudaFuncAttributeMaxDynamicSharedMemorySize, SMEM_FULL);
    cudaFuncSetAttribute(GS,   cudaFuncAttributeMaxDynamicSharedMemorySize, SMEM_FULL);
    cudaFuncSetAttribute(GAV,  cudaFuncAttributeMaxDynamicSharedMemorySize, SMEM_AV);
    cudaFuncSetAttribute(GP,   cudaFuncAttributeMaxDynamicSharedMemorySize, SMEM_FULL);

    const size_t NCb  = (size_t)N_POS * C_DIM * 4;   // packed [n][c] batch stride (bytes)
    const size_t CNb  = (size_t)C_DIM * N_POS * 4;
    const size_t NN2f = (size_t)N_POS * N_POS * 4;
    const size_t NN2h = (size_t)N_POS * N_POS * 2;
    const float scale = 0.0625f;                     // 256^-0.5

    // 1) concat weights, GroupNorm -> packed hn^T
    pack_w<<<768, 256>>>(wq, wk, wv, bq, bk, bv, wcat, bcat);
    groupnorm_kernel<<<B_DIM * G_GROUPS, 256>>>(x, gamma, beta, hnT);

    // 2) fused QKV projection (M=768, N=4096, K=256)
    GQKV<<<dim3(N_POS / 64, 6, B_DIM), 256, SMEM_FULL>>>(
        wcat, hnT, qT, kT, v16, C_DIM, C_DIM, C_DIM, 0,
        bcat, nullptr, 1.f, 0, NCb, 0);

    // 3) raw logits + per-chunk softmax stats (M=N=4096, K=256)
    GS<<<dim3(N_POS / 64, N_POS / 128, B_DIM), 256, SMEM_FULL>>>(
        qT, kT, attn, pmax, psum, C_DIM, C_DIM, C_DIM, N_POS,
        nullptr, nullptr, scale, NCb, NCb, NN2f);

    // 4) combine stats -> rmax, rinv
    combine_kernel<<<B_DIM * N_POS / 256, 256>>>(pmax, psum, rmax, rinv);

    // 5) one normalize pass: out2 (fp32 P^T) + p16 (fp16 P)
    transposeP_kernel<<<dim3(N_POS / 32, N_POS / 32, B_DIM), dim3(32, 8)>>>(
        attn, rmax, rinv, out2, p16);

    // 6) AV: hvT[n][c] = sum_m P[n][m] v[c][m]  (M=4096, N=256, K=4096)
    GAV<<<dim3(C_DIM / 64, N_POS / 128, B_DIM), 256, SMEM_AV>>>(
        p16, v16, hvT, nullptr, nullptr, N_POS, N_POS, N_POS, C_DIM,
        nullptr, nullptr, 1.f, NN2h, CNb, NCb);

    // 7) out1 = x + wp*hv + bp  (M=256, N=4096, K=256)
    GP<<<dim3(N_POS / 64, C_DIM / 128, B_DIM), 256, SMEM_FULL>>>(
        wp, hvT, out1, nullptr, nullptr, C_DIM, C_DIM, C_DIM, N_POS,
        bp, x, 1.f, 0, NCb, CNb);
}